// round 12
// baseline (speedup 1.0000x reference)
#include <cuda_runtime.h>
#include <cuda_bf16.h>
#include <cstdint>

#define MAXN 100000
#define MAXE 1600000
#define SCAN_B 1024
#define MAXSEG (2 * MAXN)

// ---------------- scratch (device globals; no runtime allocation) ----------
__device__ float g_bufA[MAXN * 128];        // 51.2 MB
__device__ float g_bufB[MAXN * 128];        // 51.2 MB
__device__ float g_bufC[MAXN * 128];        // 51.2 MB
__device__ float g_sums[MAXSEG * 128];      // 102.4 MB  per-(node,rel) means
__device__ int   g_flag[1];                 // 1 => indices are int64
// CSR over (dst,rel) segments
__device__ int   g_icnt[MAXSEG];
__device__ int   g_off[MAXSEG];
__device__ int   g_fill[MAXSEG];
__device__ int   g_bsum[256];
__device__ int   g_boff[256];
__device__ int   g_srcs[MAXE];
// pre-split, pre-transposed weights Bt[n][k], row-major bf16: [widx][hi/lo][32KB]
__device__ __align__(16) unsigned char g_wprep[5][2][32768];

__device__ __forceinline__ float* dbuf(int s) {
    return (s == 0) ? g_bufA : (s == 1) ? g_bufB : g_bufC;
}
__device__ __forceinline__ float lrelu(float v) { return v > 0.f ? v : 0.01f * v; }

// ---------------- mma.sync / cp.async helpers (sm_80+) ----------------------
__device__ __forceinline__ void ldsm_x4(uint32_t* r, uint32_t addr) {
    asm volatile("ldmatrix.sync.aligned.m8n8.x4.shared.b16 {%0,%1,%2,%3}, [%4];"
                 : "=r"(r[0]), "=r"(r[1]), "=r"(r[2]), "=r"(r[3]) : "r"(addr));
}
__device__ __forceinline__ void mma_bf16(float* c, const uint32_t* a, uint32_t b0, uint32_t b1) {
    asm volatile("mma.sync.aligned.m16n8k16.row.col.f32.bf16.bf16.f32 "
                 "{%0,%1,%2,%3}, {%4,%5,%6,%7}, {%8,%9}, {%0,%1,%2,%3};"
                 : "+f"(c[0]), "+f"(c[1]), "+f"(c[2]), "+f"(c[3])
                 : "r"(a[0]), "r"(a[1]), "r"(a[2]), "r"(a[3]), "r"(b0), "r"(b1));
}
__device__ __forceinline__ uint32_t smem_to_u32(const void* p) {
    uint32_t a;
    asm("{ .reg .u64 t; cvta.to.shared.u64 t, %1; cvt.u32.u64 %0, t; }" : "=r"(a) : "l"(p));
    return a;
}
__device__ __forceinline__ void cp_async16(uint32_t smem_addr, const void* gptr) {
    size_t ga = __cvta_generic_to_global((void*)gptr);
    asm volatile("cp.async.cg.shared.global [%0], [%1], 16;"
                 :: "r"(smem_addr), "l"(ga) : "memory");
}
__device__ __forceinline__ void cp_commit() {
    asm volatile("cp.async.commit_group;" ::: "memory");
}
__device__ __forceinline__ void cp_wait0() {
    asm volatile("cp.async.wait_group 0;" ::: "memory");
}

// SMEM tile geometry: [128 rows][136 bf16] (stride 272 B -> ldmatrix conflict-free)
#define SROW 272
#define SBUF (128 * SROW)          // 34816 B per buffer
#define OFF_AHI 0
#define OFF_ALO (SBUF)
#define OFF_B0H (2 * SBUF)
#define OFF_B1H (4 * SBUF)
#define TC_SMEM (6 * SBUF)         // 208896 B (B hi/lo double-buffered)

// ---------------- dtype detection: int64 vs int32 edge indices -------------
__global__ void detect_kernel(const int* __restrict__ ei) {
    __shared__ int s_nz;
    if (threadIdx.x == 0) s_nz = 0;
    __syncthreads();
    for (int p = threadIdx.x; p < 1024; p += blockDim.x)
        if (ei[2 * p + 1] != 0) s_nz = 1;
    __syncthreads();
    if (threadIdx.x == 0) g_flag[0] = (s_nz == 0) ? 1 : 0;
}

// ---------------- CSR build --------------------------------------------------
__global__ void zero_int_kernel(int n2) {
    int i = blockIdx.x * 256 + threadIdx.x;
    if (i < n2) { g_icnt[i] = 0; g_fill[i] = 0; }
}

__global__ void icount_kernel(const void* __restrict__ ei, const void* __restrict__ et, int E) {
    int e = blockIdx.x * 256 + threadIdx.x;
    if (e >= E) return;
    long dst, typ;
    if (g_flag[0]) {
        dst = ((const long long*)ei)[(long)E + e];
        typ = ((const long long*)et)[e];
    } else {
        dst = ((const int*)ei)[E + e];
        typ = ((const int*)et)[e];
    }
    atomicAdd(&g_icnt[dst * 2 + typ], 1);
}

__global__ void scan_block_sums(int n2) {
    __shared__ int ssum[256];
    int base = blockIdx.x * SCAN_B;
    int tsum = 0;
    for (int i = threadIdx.x; i < SCAN_B; i += 256) {
        int idx = base + i;
        tsum += (idx < n2) ? g_icnt[idx] : 0;
    }
    ssum[threadIdx.x] = tsum;
    __syncthreads();
    for (int s = 128; s > 0; s >>= 1) {
        if (threadIdx.x < s) ssum[threadIdx.x] += ssum[threadIdx.x + s];
        __syncthreads();
    }
    if (threadIdx.x == 0) g_bsum[blockIdx.x] = ssum[0];
}

__global__ void scan_tops(int nb) {
    __shared__ int sv[256];
    int t = threadIdx.x;
    sv[t] = (t < nb) ? g_bsum[t] : 0;
    __syncthreads();
    if (t == 0) {
        int run = 0;
        for (int i = 0; i < nb; i++) { int c = sv[i]; sv[i] = run; run += c; }
    }
    __syncthreads();
    if (t < nb) g_boff[t] = sv[t];
}

__global__ void scan_offsets(int n2) {
    __shared__ int warpsum[8];
    int t = threadIdx.x;
    int base = blockIdx.x * SCAN_B + t * 4;
    int v[4];
    #pragma unroll
    for (int j = 0; j < 4; j++) v[j] = (base + j < n2) ? g_icnt[base + j] : 0;
    int tsum = v[0] + v[1] + v[2] + v[3];
    int lane = t & 31, wid = t >> 5;
    int x = tsum;
    #pragma unroll
    for (int o = 1; o < 32; o <<= 1) {
        int y = __shfl_up_sync(0xFFFFFFFFu, x, o);
        if (lane >= o) x += y;
    }
    if (lane == 31) warpsum[wid] = x;
    __syncthreads();
    if (t == 0) {
        int run = 0;
        for (int i = 0; i < 8; i++) { int c = warpsum[i]; warpsum[i] = run; run += c; }
    }
    __syncthreads();
    int ex = x - tsum + warpsum[wid] + g_boff[blockIdx.x];
    #pragma unroll
    for (int j = 0; j < 4; j++) {
        if (base + j < n2) g_off[base + j] = ex;
        ex += v[j];
    }
}

__global__ void fill_kernel(const void* __restrict__ ei, const void* __restrict__ et, int E) {
    int e = blockIdx.x * 256 + threadIdx.x;
    if (e >= E) return;
    long src, dst, typ;
    if (g_flag[0]) {
        const long long* p = (const long long*)ei;
        src = p[e]; dst = p[(long)E + e];
        typ = ((const long long*)et)[e];
    } else {
        const int* p = (const int*)ei;
        src = p[e]; dst = p[E + e];
        typ = ((const int*)et)[e];
    }
    int s = (int)(dst * 2 + typ);
    int pos = atomicAdd(&g_fill[s], 1);
    g_srcs[g_off[s] + pos] = (int)src;
}

// ---------------- mean aggregation: warp per (dst,rel) segment --------------
__global__ void mean_kernel(int selX, int n2) {
    int seg = blockIdx.x * 8 + (threadIdx.x >> 5);
    int lane = threadIdx.x & 31;
    if (seg >= n2) return;
    int deg = g_icnt[seg];
    int base = g_off[seg];
    const float4* X4 = (const float4*)dbuf(selX);
    float4 acc = make_float4(0.f, 0.f, 0.f, 0.f);
    int i = 0;
    for (; i + 4 <= deg; i += 4) {
        int s0 = g_srcs[base + i], s1 = g_srcs[base + i + 1];
        int s2 = g_srcs[base + i + 2], s3 = g_srcs[base + i + 3];
        float4 v0 = X4[(long)s0 * 32 + lane];
        float4 v1 = X4[(long)s1 * 32 + lane];
        float4 v2 = X4[(long)s2 * 32 + lane];
        float4 v3 = X4[(long)s3 * 32 + lane];
        acc.x += v0.x + v1.x + v2.x + v3.x;
        acc.y += v0.y + v1.y + v2.y + v3.y;
        acc.z += v0.z + v1.z + v2.z + v3.z;
        acc.w += v0.w + v1.w + v2.w + v3.w;
    }
    for (; i < deg; i++) {
        int s0 = g_srcs[base + i];
        float4 v0 = X4[(long)s0 * 32 + lane];
        acc.x += v0.x; acc.y += v0.y; acc.z += v0.z; acc.w += v0.w;
    }
    float sc = 1.0f / (float)max(deg, 1);
    acc.x *= sc; acc.y *= sc; acc.z *= sc; acc.w *= sc;
    ((float4*)g_sums)[(long)seg * 32 + lane] = acc;
}

// ---------------- weight prep: W[128,128] -> Bt[n][k] bf16 hi/lo ------------
__global__ void wprep_kernel(const float* __restrict__ Win, const float* __restrict__ Wrel,
                             const float* __restrict__ Wroot, const float* __restrict__ Wo1) {
    int w = blockIdx.x;
    const float* W = (w == 0) ? Win : (w == 1) ? Wrel : (w == 2) ? (Wrel + 16384)
                   : (w == 3) ? Wroot : Wo1;
    unsigned char* hi = g_wprep[w][0];
    unsigned char* lo = g_wprep[w][1];
    for (int i = threadIdx.x; i < 4096; i += blockDim.x) {
        int nrow = i >> 5;
        int k0 = (i & 31) * 4;
        unsigned short hs[4], ls[4];
        #pragma unroll
        for (int j = 0; j < 4; j++) {
            float x = W[(k0 + j) * 128 + nrow];   // Bt[n][k] = W[k][n]
            __nv_bfloat16 h = __float2bfloat16_rn(x);
            float rl = x - __bfloat162float(h);
            __nv_bfloat16 l = __float2bfloat16_rn(rl);
            hs[j] = __bfloat16_as_ushort(h);
            ls[j] = __bfloat16_as_ushort(l);
        }
        uint32_t off = (uint32_t)nrow * 256u + (uint32_t)k0 * 2u;
        uint2 uh, ul;
        uh.x = (uint32_t)hs[0] | ((uint32_t)hs[1] << 16);
        uh.y = (uint32_t)hs[2] | ((uint32_t)hs[3] << 16);
        ul.x = (uint32_t)ls[0] | ((uint32_t)ls[1] << 16);
        ul.y = (uint32_t)ls[2] | ((uint32_t)ls[3] << 16);
        *(uint2*)(hi + off) = uh;
        *(uint2*)(lo + off) = ul;
    }
}

// ---------------- feature fusion: K=100 register-blocked kernel -------------
// 256 threads, 128 nodes/block. Thread: 4 nodes x 4 cols. Dynamic smem.
__global__ void fuse100_kernel(const float* __restrict__ des, const float* __restrict__ tw,
                               const float* __restrict__ Wd, const float* __restrict__ bd,
                               const float* __restrict__ Wt, const float* __restrict__ bt,
                               int n) {
    extern __shared__ float fsm[];
    float* sW = fsm;                 // 100*32 = 3200
    float* sIn = fsm + 3200;         // 128*100 = 12800
    float* sB = fsm + 3200 + 12800;  // 32
    int tid = threadIdx.x;
    int n0 = blockIdx.x * 128;
    int seg = blockIdx.y;
    const float* in = seg ? tw : des;
    const float* W = seg ? Wt : Wd;
    const float* B = seg ? bt : bd;

    for (int i = tid; i < 3200; i += 256) sW[i] = W[i];
    if (tid < 32) sB[tid] = B[tid];
    const float4* in4 = (const float4*)in;
    float4* sIn4 = (float4*)sIn;
    for (int i = tid; i < 128 * 25; i += 256) {
        int r = i / 25, c = i - r * 25;
        int row = n0 + r;
        sIn4[i] = (row < n) ? in4[(long)row * 25 + c] : make_float4(0.f, 0.f, 0.f, 0.f);
    }
    __syncthreads();

    int ng = tid >> 3;          // 0..31  (node group of 4)
    int cg = tid & 7;           // 0..7   (col group of 4)
    int c0 = cg * 4;
    float acc[4][4];
    #pragma unroll
    for (int j = 0; j < 4; j++) {
        acc[j][0] = sB[c0]; acc[j][1] = sB[c0 + 1];
        acc[j][2] = sB[c0 + 2]; acc[j][3] = sB[c0 + 3];
    }
    const float4* sW4 = (const float4*)sW;
    const float* a0 = sIn + (ng * 4 + 0) * 100;
    const float* a1 = sIn + (ng * 4 + 1) * 100;
    const float* a2 = sIn + (ng * 4 + 2) * 100;
    const float* a3 = sIn + (ng * 4 + 3) * 100;
    #pragma unroll 4
    for (int k = 0; k < 100; k++) {
        float4 wv = sW4[k * 8 + cg];
        float x0 = a0[k], x1 = a1[k], x2 = a2[k], x3 = a3[k];
        acc[0][0] += x0 * wv.x; acc[0][1] += x0 * wv.y; acc[0][2] += x0 * wv.z; acc[0][3] += x0 * wv.w;
        acc[1][0] += x1 * wv.x; acc[1][1] += x1 * wv.y; acc[1][2] += x1 * wv.z; acc[1][3] += x1 * wv.w;
        acc[2][0] += x2 * wv.x; acc[2][1] += x2 * wv.y; acc[2][2] += x2 * wv.z; acc[2][3] += x2 * wv.w;
        acc[3][0] += x3 * wv.x; acc[3][1] += x3 * wv.y; acc[3][2] += x3 * wv.z; acc[3][3] += x3 * wv.w;
    }
    #pragma unroll
    for (int j = 0; j < 4; j++) {
        int row = n0 + ng * 4 + j;
        if (row < n) {
            float4 o;
            o.x = lrelu(acc[j][0]); o.y = lrelu(acc[j][1]);
            o.z = lrelu(acc[j][2]); o.w = lrelu(acc[j][3]);
            *(float4*)(g_bufA + (long)row * 128 + seg * 32 + c0) = o;
        }
    }
}

// ---------------- feature fusion: small K (6, 11) ---------------------------
template<int K>
__device__ __forceinline__ void fuse_seg(const float* __restrict__ in,
                                         const float* __restrict__ W,
                                         const float* __restrict__ B,
                                         float* sW, float* sB, float* sIn,
                                         int n0, int n, int tid, int seg) {
    for (int i = tid; i < K * 32; i += 256) sW[i] = W[i];
    if (tid < 32) sB[tid] = B[tid];
    for (int i = tid; i < 64 * K; i += 256) {
        int r = i / K, c = i - r * K;
        int row = n0 + r;
        sIn[i] = (row < n) ? in[(long)row * K + c] : 0.f;
    }
    __syncthreads();

    int node = tid >> 2;
    int c0 = (tid & 3) * 8;
    float acc[8];
    #pragma unroll
    for (int j = 0; j < 8; j++) acc[j] = sB[c0 + j];
    const float4* sW4 = (const float4*)sW;
    int wbase = c0 >> 2;
    const float* aIn = sIn + node * K;
    #pragma unroll
    for (int k = 0; k < K; k++) {
        float a = aIn[k];
        float4 w0 = sW4[k * 8 + wbase];
        float4 w1 = sW4[k * 8 + wbase + 1];
        acc[0] += a * w0.x; acc[1] += a * w0.y; acc[2] += a * w0.z; acc[3] += a * w0.w;
        acc[4] += a * w1.x; acc[5] += a * w1.y; acc[6] += a * w1.z; acc[7] += a * w1.w;
    }
    int row = n0 + node;
    if (row < n) {
        float* o = g_bufA + (long)row * 128 + seg * 32 + c0;
        #pragma unroll
        for (int j = 0; j < 8; j++) o[j] = lrelu(acc[j]);
    }
}

__global__ void fuse_small_kernel(const float* __restrict__ nprop, const float* __restrict__ cprop,
                                  const float* __restrict__ Wn, const float* __restrict__ bn,
                                  const float* __restrict__ Wc, const float* __restrict__ bc,
                                  int n) {
    __shared__ __align__(16) float sW[11 * 32];
    __shared__ float sB[32];
    __shared__ __align__(16) float sIn[64 * 11];
    int tid = threadIdx.x;
    int n0 = blockIdx.x * 64;
    if (blockIdx.y == 0) fuse_seg<6> (nprop, Wn, bn, sW, sB, sIn, n0, n, tid, 2);
    else                 fuse_seg<11>(cprop, Wc, bc, sW, sB, sIn, n0, n, tid, 3);
}

// ---------------- mma.sync GEMM (software-pipelined) ------------------------
// 512 threads / 16 warps. Warp w: rows (w>>1)*16..+15, cols (w&1)*64..+63.
// mode 0: 1 pass, A = dbuf(selX), weight w0.
// mode 1: 3 passes: p<2 A = g_sums rows (means); p=2 A = dbuf(selX).
// B hi/lo double-buffered via cp.async; next-pass A prefetched to registers
// before compute so DRAM latency hides under the mma loop.
__global__ __launch_bounds__(512, 1)
void tc_gemm(int mode, int selX, int selC, int w0, int w1, int w2,
             const float* __restrict__ bias, int act, int n,
             const float* __restrict__ Wo2, const float* __restrict__ bo2,
             float* __restrict__ out2, int head) {
    extern __shared__ unsigned char smm[];
    uint32_t sbase = smem_to_u32(smm);
    int tid = threadIdx.x;
    int w = tid >> 5;
    int l = tid & 31;
    int rw = (w >> 1) * 16;
    int cb = (w & 1) * 64;
    int n0 = blockIdx.x * 128;

    float acc[8][4];
    #pragma unroll
    for (int t = 0; t < 8; t++) { acc[t][0] = acc[t][1] = acc[t][2] = acc[t][3] = 0.f; }

    uint32_t aRow = (uint32_t)(rw + (l & 15));
    uint32_t aAddrHi = sbase + OFF_AHI + aRow * SROW + ((uint32_t)(l >> 4)) * 16u;
    uint32_t aAddrLo = aAddrHi + (OFF_ALO - OFF_AHI);
    uint32_t bN = (uint32_t)(cb + (l & 7) + ((l >> 4) << 3));
    uint32_t bOff = bN * SROW + ((uint32_t)((l >> 3) & 1)) * 16u;

    int npass = (mode == 1) ? 3 : 1;
    const float4* X4 = (const float4*)dbuf(selX);
    float4 va[8];

    // ---- helpers (inlined manually) ----
    #define STAGE_B(widx, buf) do {                                             \
        const uint4* _bh = (const uint4*)g_wprep[widx][0];                      \
        const uint4* _bl = (const uint4*)g_wprep[widx][1];                      \
        uint32_t _bb = sbase + ((buf) ? OFF_B1H : OFF_B0H);                     \
        _Pragma("unroll")                                                       \
        for (int _j = 0; _j < 4; _j++) {                                        \
            int _i = tid + _j * 512;                                            \
            uint32_t _r = (uint32_t)(_i >> 4), _c = (uint32_t)(_i & 15);        \
            uint32_t _o = _r * SROW + _c * 16u;                                 \
            cp_async16(_bb + _o, _bh + _i);                                     \
            cp_async16(_bb + SBUF + _o, _bl + _i);                              \
        }                                                                       \
        cp_commit();                                                            \
    } while (0)

    #define LOAD_A(p) do {                                                      \
        bool _fs = (mode == 1 && (p) < 2);                                      \
        _Pragma("unroll")                                                       \
        for (int _j = 0; _j < 8; _j++) {                                        \
            int _i = tid + _j * 512;                                            \
            int _r = _i >> 5, _cg = _i & 31;                                    \
            int _row = n0 + _r;                                                 \
            va[_j] = make_float4(0.f, 0.f, 0.f, 0.f);                           \
            if (_row < n) {                                                     \
                if (_fs) va[_j] = ((const float4*)g_sums)[((long)_row * 2 + (p)) * 32 + _cg]; \
                else     va[_j] = X4[(long)_row * 32 + _cg];                    \
            }                                                                   \
        }                                                                       \
    } while (0)

    #define CONV_STS() do {                                                     \
        _Pragma("unroll")                                                       \
        for (int _j = 0; _j < 8; _j++) {                                        \
            int _i = tid + _j * 512;                                            \
            int _r = _i >> 5, _cg = _i & 31;                                    \
            float _x[4] = {va[_j].x, va[_j].y, va[_j].z, va[_j].w};             \
            unsigned short _hs[4], _ls[4];                                      \
            _Pragma("unroll")                                                   \
            for (int _q = 0; _q < 4; _q++) {                                    \
                __nv_bfloat16 _h = __float2bfloat16_rn(_x[_q]);                 \
                float _rl = _x[_q] - __bfloat162float(_h);                      \
                __nv_bfloat16 _lw = __float2bfloat16_rn(_rl);                   \
                _hs[_q] = __bfloat16_as_ushort(_h);                             \
                _ls[_q] = __bfloat16_as_ushort(_lw);                            \
            }                                                                   \
            uint32_t _o = (uint32_t)_r * SROW + (uint32_t)_cg * 8u;             \
            uint2 _uh, _ul;                                                     \
            _uh.x = (uint32_t)_hs[0] | ((uint32_t)_hs[1] << 16);                \
            _uh.y = (uint32_t)_hs[2] | ((uint32_t)_hs[3] << 16);                \
            _ul.x = (uint32_t)_ls[0] | ((uint32_t)_ls[1] << 16);                \
            _ul.y = (uint32_t)_ls[2] | ((uint32_t)_ls[3] << 16);                \
            *(uint2*)(smm + OFF_AHI + _o) = _uh;                                \
            *(uint2*)(smm + OFF_ALO + _o) = _ul;                                \
        }                                                                       \
    } while (0)

    // ---- prologue: pass 0 ----
    STAGE_B(w0, 0);
    LOAD_A(0);
    CONV_STS();
    cp_wait0();
    __syncthreads();

    for (int p = 0; p < npass; p++) {
        if (p + 1 < npass) {
            int widx = (p + 1 == 1) ? w1 : w2;
            STAGE_B(widx, (p + 1) & 1);
            LOAD_A(p + 1);
        }
        // compute pass p
        uint32_t bH = sbase + ((p & 1) ? OFF_B1H : OFF_B0H) + bOff;
        uint32_t bL = bH + SBUF;
        for (int k0 = 0; k0 < 8; k0++) {
            uint32_t ah[4], al[4];
            ldsm_x4(ah, aAddrHi + (uint32_t)k0 * 32u);
            ldsm_x4(al, aAddrLo + (uint32_t)k0 * 32u);
            #pragma unroll
            for (int ng = 0; ng < 4; ng++) {
                uint32_t bhf[4], blf[4];
                uint32_t boff2 = (uint32_t)ng * (16u * SROW) + (uint32_t)k0 * 32u;
                ldsm_x4(bhf, bH + boff2);
                ldsm_x4(blf, bL + boff2);
                mma_bf16(acc[2 * ng],     ah, bhf[0], bhf[1]);
                mma_bf16(acc[2 * ng],     ah, blf[0], blf[1]);
                mma_bf16(acc[2 * ng],     al, bhf[0], bhf[1]);
                mma_bf16(acc[2 * ng + 1], ah, bhf[2], bhf[3]);
                mma_bf16(acc[2 * ng + 1], ah, blf[2], blf[3]);
                mma_bf16(acc[2 * ng + 1], al, bhf[2], bhf[3]);
            }
        }
        if (p + 1 < npass) {
            __syncthreads();      // compute p done -> A buffer reusable
            CONV_STS();
            cp_wait0();           // B(p+1) arrived
            __syncthreads();
        }
    }

    if (head) {
        // fused head: out2[row] = lrelu(acc+bias) @ Wo2 + bo2
        float p00 = 0.f, p01 = 0.f, p10 = 0.f, p11 = 0.f;
        #pragma unroll
        for (int t = 0; t < 8; t++) {
            int col = cb + t * 8 + (l & 3) * 2;
            float b0 = bias[col], b1 = bias[col + 1];
            float w00 = Wo2[col * 2], w01 = Wo2[col * 2 + 1];
            float w10 = Wo2[(col + 1) * 2], w11 = Wo2[(col + 1) * 2 + 1];
            float o0 = lrelu(acc[t][0] + b0), o1 = lrelu(acc[t][1] + b1);
            p00 += o0 * w00 + o1 * w10;  p01 += o0 * w01 + o1 * w11;
            float o2 = lrelu(acc[t][2] + b0), o3 = lrelu(acc[t][3] + b1);
            p10 += o2 * w00 + o3 * w10;  p11 += o2 * w01 + o3 * w11;
        }
        #pragma unroll
        for (int m = 1; m <= 2; m <<= 1) {
            p00 += __shfl_xor_sync(0xFFFFFFFFu, p00, m);
            p01 += __shfl_xor_sync(0xFFFFFFFFu, p01, m);
            p10 += __shfl_xor_sync(0xFFFFFFFFu, p10, m);
            p11 += __shfl_xor_sync(0xFFFFFFFFu, p11, m);
        }
        __syncthreads();
        float* scratch = (float*)(smm + OFF_AHI);
        int rr0 = rw + (l >> 2);
        if ((w & 1) == 0 && (l & 3) == 0) {
            scratch[rr0 * 2 + 0] = p00;  scratch[rr0 * 2 + 1] = p01;
            scratch[(rr0 + 8) * 2 + 0] = p10;  scratch[(rr0 + 8) * 2 + 1] = p11;
        }
        __syncthreads();
        if ((w & 1) == 1 && (l & 3) == 0) {
            int row0 = n0 + rr0, row1 = row0 + 8;
            float c0 = bo2[0], c1 = bo2[1];
            if (row0 < n) {
                out2[row0 * 2 + 0] = scratch[rr0 * 2 + 0] + p00 + c0;
                out2[row0 * 2 + 1] = scratch[rr0 * 2 + 1] + p01 + c1;
            }
            if (row1 < n) {
                out2[row1 * 2 + 0] = scratch[(rr0 + 8) * 2 + 0] + p10 + c0;
                out2[row1 * 2 + 1] = scratch[(rr0 + 8) * 2 + 1] + p11 + c1;
            }
        }
        return;
    }

    float* C = dbuf(selC);
    int r0 = n0 + rw + (l >> 2);
    int r1 = r0 + 8;
    #pragma unroll
    for (int t = 0; t < 8; t++) {
        int col = cb + t * 8 + (l & 3) * 2;
        float b0 = bias[col], b1 = bias[col + 1];
        if (r0 < n) {
            float2 o;
            o.x = acc[t][0] + b0; o.y = acc[t][1] + b1;
            if (act) { o.x = lrelu(o.x); o.y = lrelu(o.y); }
            *(float2*)(C + (long)r0 * 128 + col) = o;
        }
        if (r1 < n) {
            float2 o;
            o.x = acc[t][2] + b0; o.y = acc[t][3] + b1;
            if (act) { o.x = lrelu(o.x); o.y = lrelu(o.y); }
            *(float2*)(C + (long)r1 * 128 + col) = o;
        }
    }
}

// ---------------- host ------------------------------------------------------
extern "C" void kernel_launch(void* const* d_in, const int* in_sizes, int n_in,
                              void* d_out, int out_size) {
    const float* des  = (const float*)d_in[0];
    const float* tw   = (const float*)d_in[1];
    const float* npr  = (const float*)d_in[2];
    const float* cpr  = (const float*)d_in[3];
    const void*  ei   = d_in[4];
    const void*  et   = d_in[5];
    const float* Wd   = (const float*)d_in[6];  const float* bd  = (const float*)d_in[7];
    const float* Wt   = (const float*)d_in[8];  const float* bt  = (const float*)d_in[9];
    const float* Wn   = (const float*)d_in[10]; const float* bn  = (const float*)d_in[11];
    const float* Wc   = (const float*)d_in[12]; const float* bc  = (const float*)d_in[13];
    const float* Win  = (const float*)d_in[14]; const float* bin = (const float*)d_in[15];
    const float* Wrel = (const float*)d_in[16];
    const float* Wroot= (const float*)d_in[17];
    const float* brg  = (const float*)d_in[18];
    const float* Wo1  = (const float*)d_in[19]; const float* bo1 = (const float*)d_in[20];
    const float* Wo2  = (const float*)d_in[21]; const float* bo2 = (const float*)d_in[22];
    float* out = (float*)d_out;

    int N = in_sizes[0] / 100;
    int E = in_sizes[5];
    int n2 = 2 * N;
    int nb_scan = (n2 + SCAN_B - 1) / SCAN_B;

    const int FUSE_SMEM = (3200 + 12800 + 32) * 4;   // 64128 B
    cudaFuncSetAttribute(tc_gemm, cudaFuncAttributeMaxDynamicSharedMemorySize, TC_SMEM);
    cudaFuncSetAttribute(fuse100_kernel, cudaFuncAttributeMaxDynamicSharedMemorySize, FUSE_SMEM);

    int nb64 = (N + 63) / 64;
    int nb128 = (N + 127) / 128;
    int eb = (E + 255) / 256;

    detect_kernel<<<1, 256>>>((const int*)ei);
    wprep_kernel<<<5, 256>>>(Win, Wrel, Wroot, Wo1);

    // CSR build (once; reused by both layers)
    zero_int_kernel<<<(n2 + 255) / 256, 256>>>(n2);
    icount_kernel<<<eb, 256>>>(ei, et, E);
    scan_block_sums<<<nb_scan, 256>>>(n2);
    scan_tops<<<1, 256>>>(nb_scan);
    scan_offsets<<<nb_scan, 256>>>(n2);
    fill_kernel<<<eb, 256>>>(ei, et, E);

    fuse100_kernel<<<dim3(nb128, 2), 256, FUSE_SMEM>>>(des, tw, Wd, bd, Wt, bt, N);
    fuse_small_kernel<<<dim3(nb64, 2), 256>>>(npr, cpr, Wn, bn, Wc, bc, N);
    tc_gemm<<<nb128, 512, TC_SMEM>>>(0, 0, 1, 0, 0, 0, bin, 1, N, 0, 0, 0, 0);  // bufA -> bufB

    mean_kernel<<<(n2 + 7) / 8, 256>>>(1, n2);                                   // x0 means
    tc_gemm<<<nb128, 512, TC_SMEM>>>(1, 1, 2, 1, 2, 3, brg, 0, N, 0, 0, 0, 0);  // -> bufC

    mean_kernel<<<(n2 + 7) / 8, 256>>>(2, n2);                                   // x1 means
    tc_gemm<<<nb128, 512, TC_SMEM>>>(1, 2, 0, 1, 2, 3, brg, 0, N, 0, 0, 0, 0);  // -> bufA

    // head: GEMM(Wo1)+lrelu fused with @Wo2+b2 -> out
    tc_gemm<<<nb128, 512, TC_SMEM>>>(0, 0, 1, 4, 0, 0, bo1, 1, N, Wo2, bo2, out, 1);
}

// round 14
// speedup vs baseline: 1.0411x; 1.0411x over previous
#include <cuda_runtime.h>
#include <cuda_bf16.h>
#include <cstdint>

#define MAXN 100000
#define MAXE 1600000
#define SCAN_B 1024
#define MAXSEG (2 * MAXN)

// ---------------- scratch (device globals; no runtime allocation) ----------
__device__ float g_bufA[MAXN * 128];        // 51.2 MB
__device__ float g_bufB[MAXN * 128];        // 51.2 MB
__device__ float g_bufC[MAXN * 128];        // 51.2 MB
__device__ float g_sums[MAXSEG * 128];      // 102.4 MB  per-(node,rel) means
__device__ int   g_flag[1];                 // 1 => indices are int64
// CSR over (dst,rel) segments
__device__ int   g_icnt[MAXSEG];
__device__ int   g_off[MAXSEG];
__device__ int   g_fill[MAXSEG];
__device__ int   g_bsum[256];
__device__ int   g_boff[256];
__device__ int   g_srcs[MAXE];
// pre-split, pre-transposed weights Bt[n][k], row-major bf16: [widx][hi/lo][32KB]
__device__ __align__(16) unsigned char g_wprep[5][2][32768];

__device__ __forceinline__ float* dbuf(int s) {
    return (s == 0) ? g_bufA : (s == 1) ? g_bufB : g_bufC;
}
__device__ __forceinline__ float lrelu(float v) { return v > 0.f ? v : 0.01f * v; }

// ---------------- mma.sync / cp.async helpers (sm_80+) ----------------------
__device__ __forceinline__ void ldsm_x4(uint32_t* r, uint32_t addr) {
    asm volatile("ldmatrix.sync.aligned.m8n8.x4.shared.b16 {%0,%1,%2,%3}, [%4];"
                 : "=r"(r[0]), "=r"(r[1]), "=r"(r[2]), "=r"(r[3]) : "r"(addr));
}
__device__ __forceinline__ void mma_bf16(float* c, const uint32_t* a, uint32_t b0, uint32_t b1) {
    asm volatile("mma.sync.aligned.m16n8k16.row.col.f32.bf16.bf16.f32 "
                 "{%0,%1,%2,%3}, {%4,%5,%6,%7}, {%8,%9}, {%0,%1,%2,%3};"
                 : "+f"(c[0]), "+f"(c[1]), "+f"(c[2]), "+f"(c[3])
                 : "r"(a[0]), "r"(a[1]), "r"(a[2]), "r"(a[3]), "r"(b0), "r"(b1));
}
__device__ __forceinline__ uint32_t smem_to_u32(const void* p) {
    uint32_t a;
    asm("{ .reg .u64 t; cvta.to.shared.u64 t, %1; cvt.u32.u64 %0, t; }" : "=r"(a) : "l"(p));
    return a;
}
__device__ __forceinline__ void cp_async16(uint32_t smem_addr, const void* gptr) {
    size_t ga = __cvta_generic_to_global((void*)gptr);
    asm volatile("cp.async.cg.shared.global [%0], [%1], 16;"
                 :: "r"(smem_addr), "l"(ga) : "memory");
}
__device__ __forceinline__ void cp_async_wait_all() {
    asm volatile("cp.async.commit_group;\ncp.async.wait_group 0;" ::: "memory");
}

// SMEM tile geometry: [128 rows][136 bf16] (stride 272 B -> ldmatrix conflict-free)
#define SROW 272
#define SBUF (128 * SROW)          // 34816 B per buffer
#define OFF_AHI 0
#define OFF_ALO (SBUF)
#define OFF_BHI (2 * SBUF)
#define OFF_BLO (3 * SBUF)
#define TC_SMEM (4 * SBUF)         // 139264 B

// ---------------- dtype detection + CSR zeroing -----------------------------
__global__ void detect_kernel(const int* __restrict__ ei, int n2) {
    __shared__ int s_nz;
    if (blockIdx.x == 0) {
        if (threadIdx.x == 0) s_nz = 0;
        __syncthreads();
        for (int p = threadIdx.x; p < 1024; p += blockDim.x)
            if (ei[2 * p + 1] != 0) s_nz = 1;
        __syncthreads();
        if (threadIdx.x == 0) g_flag[0] = (s_nz == 0) ? 1 : 0;
    }
    int i = blockIdx.x * 256 + threadIdx.x;
    if (i < n2) { g_icnt[i] = 0; g_fill[i] = 0; }
}

// ---------------- CSR build --------------------------------------------------
__global__ void icount_kernel(const void* __restrict__ ei, const void* __restrict__ et, int E) {
    int e = blockIdx.x * 256 + threadIdx.x;
    if (e >= E) return;
    long dst, typ;
    if (g_flag[0]) {
        dst = ((const long long*)ei)[(long)E + e];
        typ = ((const long long*)et)[e];
    } else {
        dst = ((const int*)ei)[E + e];
        typ = ((const int*)et)[e];
    }
    atomicAdd(&g_icnt[dst * 2 + typ], 1);
}

__global__ void scan_block_sums(int n2) {
    __shared__ int ssum[256];
    int base = blockIdx.x * SCAN_B;
    int tsum = 0;
    for (int i = threadIdx.x; i < SCAN_B; i += 256) {
        int idx = base + i;
        tsum += (idx < n2) ? g_icnt[idx] : 0;
    }
    ssum[threadIdx.x] = tsum;
    __syncthreads();
    for (int s = 128; s > 0; s >>= 1) {
        if (threadIdx.x < s) ssum[threadIdx.x] += ssum[threadIdx.x + s];
        __syncthreads();
    }
    if (threadIdx.x == 0) g_bsum[blockIdx.x] = ssum[0];
}

__global__ void scan_tops(int nb) {
    __shared__ int sv[256];
    int t = threadIdx.x;
    sv[t] = (t < nb) ? g_bsum[t] : 0;
    __syncthreads();
    if (t == 0) {
        int run = 0;
        for (int i = 0; i < nb; i++) { int c = sv[i]; sv[i] = run; run += c; }
    }
    __syncthreads();
    if (t < nb) g_boff[t] = sv[t];
}

__global__ void scan_offsets(int n2) {
    __shared__ int warpsum[8];
    int t = threadIdx.x;
    int base = blockIdx.x * SCAN_B + t * 4;
    int v[4];
    #pragma unroll
    for (int j = 0; j < 4; j++) v[j] = (base + j < n2) ? g_icnt[base + j] : 0;
    int tsum = v[0] + v[1] + v[2] + v[3];
    int lane = t & 31, wid = t >> 5;
    int x = tsum;
    #pragma unroll
    for (int o = 1; o < 32; o <<= 1) {
        int y = __shfl_up_sync(0xFFFFFFFFu, x, o);
        if (lane >= o) x += y;
    }
    if (lane == 31) warpsum[wid] = x;
    __syncthreads();
    if (t == 0) {
        int run = 0;
        for (int i = 0; i < 8; i++) { int c = warpsum[i]; warpsum[i] = run; run += c; }
    }
    __syncthreads();
    int ex = x - tsum + warpsum[wid] + g_boff[blockIdx.x];
    #pragma unroll
    for (int j = 0; j < 4; j++) {
        if (base + j < n2) g_off[base + j] = ex;
        ex += v[j];
    }
}

__global__ void fill_kernel(const void* __restrict__ ei, const void* __restrict__ et, int E) {
    int e = blockIdx.x * 256 + threadIdx.x;
    if (e >= E) return;
    long src, dst, typ;
    if (g_flag[0]) {
        const long long* p = (const long long*)ei;
        src = p[e]; dst = p[(long)E + e];
        typ = ((const long long*)et)[e];
    } else {
        const int* p = (const int*)ei;
        src = p[e]; dst = p[E + e];
        typ = ((const int*)et)[e];
    }
    int s = (int)(dst * 2 + typ);
    int pos = atomicAdd(&g_fill[s], 1);
    g_srcs[g_off[s] + pos] = (int)src;
}

// ---------------- mean aggregation: warp per (dst,rel) segment --------------
__global__ void mean_kernel(int selX, int n2) {
    int seg = blockIdx.x * 8 + (threadIdx.x >> 5);
    int lane = threadIdx.x & 31;
    if (seg >= n2) return;
    int deg = g_icnt[seg];
    int base = g_off[seg];
    const float4* X4 = (const float4*)dbuf(selX);
    float4 acc = make_float4(0.f, 0.f, 0.f, 0.f);
    int i = 0;
    for (; i + 4 <= deg; i += 4) {
        int s0 = g_srcs[base + i], s1 = g_srcs[base + i + 1];
        int s2 = g_srcs[base + i + 2], s3 = g_srcs[base + i + 3];
        float4 v0 = X4[(long)s0 * 32 + lane];
        float4 v1 = X4[(long)s1 * 32 + lane];
        float4 v2 = X4[(long)s2 * 32 + lane];
        float4 v3 = X4[(long)s3 * 32 + lane];
        acc.x += v0.x + v1.x + v2.x + v3.x;
        acc.y += v0.y + v1.y + v2.y + v3.y;
        acc.z += v0.z + v1.z + v2.z + v3.z;
        acc.w += v0.w + v1.w + v2.w + v3.w;
    }
    for (; i < deg; i++) {
        int s0 = g_srcs[base + i];
        float4 v0 = X4[(long)s0 * 32 + lane];
        acc.x += v0.x; acc.y += v0.y; acc.z += v0.z; acc.w += v0.w;
    }
    float sc = 1.0f / (float)max(deg, 1);
    acc.x *= sc; acc.y *= sc; acc.z *= sc; acc.w *= sc;
    ((float4*)g_sums)[(long)seg * 32 + lane] = acc;
}

// ---------------- weight prep: W[128,128] -> Bt[n][k] bf16 hi/lo ------------
__global__ void wprep_kernel(const float* __restrict__ Win, const float* __restrict__ Wrel,
                             const float* __restrict__ Wroot, const float* __restrict__ Wo1) {
    int w = blockIdx.x;
    const float* W = (w == 0) ? Win : (w == 1) ? Wrel : (w == 2) ? (Wrel + 16384)
                   : (w == 3) ? Wroot : Wo1;
    unsigned char* hi = g_wprep[w][0];
    unsigned char* lo = g_wprep[w][1];
    for (int i = threadIdx.x; i < 4096; i += blockDim.x) {
        int nrow = i >> 5;
        int k0 = (i & 31) * 4;
        unsigned short hs[4], ls[4];
        #pragma unroll
        for (int j = 0; j < 4; j++) {
            float x = W[(k0 + j) * 128 + nrow];   // Bt[n][k] = W[k][n]
            __nv_bfloat16 h = __float2bfloat16_rn(x);
            float rl = x - __bfloat162float(h);
            __nv_bfloat16 l = __float2bfloat16_rn(rl);
            hs[j] = __bfloat16_as_ushort(h);
            ls[j] = __bfloat16_as_ushort(l);
        }
        uint32_t off = (uint32_t)nrow * 256u + (uint32_t)k0 * 2u;
        uint2 uh, ul;
        uh.x = (uint32_t)hs[0] | ((uint32_t)hs[1] << 16);
        uh.y = (uint32_t)hs[2] | ((uint32_t)hs[3] << 16);
        ul.x = (uint32_t)ls[0] | ((uint32_t)ls[1] << 16);
        ul.y = (uint32_t)ls[2] | ((uint32_t)ls[3] << 16);
        *(uint2*)(hi + off) = uh;
        *(uint2*)(lo + off) = ul;
    }
}

// ---------------- feature fusion: K=100 register-blocked kernel -------------
// 256 threads, 128 nodes/block. Thread: 4 nodes x 4 cols. Dynamic smem.
__global__ void fuse100_kernel(const float* __restrict__ des, const float* __restrict__ tw,
                               const float* __restrict__ Wd, const float* __restrict__ bd,
                               const float* __restrict__ Wt, const float* __restrict__ bt,
                               int n) {
    extern __shared__ float fsm[];
    float* sW = fsm;                 // 100*32 = 3200
    float* sIn = fsm + 3200;         // 128*100 = 12800
    float* sB = fsm + 3200 + 12800;  // 32
    int tid = threadIdx.x;
    int n0 = blockIdx.x * 128;
    int seg = blockIdx.y;
    const float* in = seg ? tw : des;
    const float* W = seg ? Wt : Wd;
    const float* B = seg ? bt : bd;

    for (int i = tid; i < 3200; i += 256) sW[i] = W[i];
    if (tid < 32) sB[tid] = B[tid];
    const float4* in4 = (const float4*)in;
    float4* sIn4 = (float4*)sIn;
    for (int i = tid; i < 128 * 25; i += 256) {
        int r = i / 25, c = i - r * 25;
        int row = n0 + r;
        sIn4[i] = (row < n) ? in4[(long)row * 25 + c] : make_float4(0.f, 0.f, 0.f, 0.f);
    }
    __syncthreads();

    int ng = tid >> 3;          // 0..31  (node group of 4)
    int cg = tid & 7;           // 0..7   (col group of 4)
    int c0 = cg * 4;
    float acc[4][4];
    #pragma unroll
    for (int j = 0; j < 4; j++) {
        acc[j][0] = sB[c0]; acc[j][1] = sB[c0 + 1];
        acc[j][2] = sB[c0 + 2]; acc[j][3] = sB[c0 + 3];
    }
    const float4* sW4 = (const float4*)sW;
    const float* a0 = sIn + (ng * 4 + 0) * 100;
    const float* a1 = sIn + (ng * 4 + 1) * 100;
    const float* a2 = sIn + (ng * 4 + 2) * 100;
    const float* a3 = sIn + (ng * 4 + 3) * 100;
    #pragma unroll 4
    for (int k = 0; k < 100; k++) {
        float4 wv = sW4[k * 8 + cg];
        float x0 = a0[k], x1 = a1[k], x2 = a2[k], x3 = a3[k];
        acc[0][0] += x0 * wv.x; acc[0][1] += x0 * wv.y; acc[0][2] += x0 * wv.z; acc[0][3] += x0 * wv.w;
        acc[1][0] += x1 * wv.x; acc[1][1] += x1 * wv.y; acc[1][2] += x1 * wv.z; acc[1][3] += x1 * wv.w;
        acc[2][0] += x2 * wv.x; acc[2][1] += x2 * wv.y; acc[2][2] += x2 * wv.z; acc[2][3] += x2 * wv.w;
        acc[3][0] += x3 * wv.x; acc[3][1] += x3 * wv.y; acc[3][2] += x3 * wv.z; acc[3][3] += x3 * wv.w;
    }
    #pragma unroll
    for (int j = 0; j < 4; j++) {
        int row = n0 + ng * 4 + j;
        if (row < n) {
            float4 o;
            o.x = lrelu(acc[j][0]); o.y = lrelu(acc[j][1]);
            o.z = lrelu(acc[j][2]); o.w = lrelu(acc[j][3]);
            *(float4*)(g_bufA + (long)row * 128 + seg * 32 + c0) = o;
        }
    }
}

// ---------------- feature fusion: small K (6, 11) ---------------------------
template<int K>
__device__ __forceinline__ void fuse_seg(const float* __restrict__ in,
                                         const float* __restrict__ W,
                                         const float* __restrict__ B,
                                         float* sW, float* sB, float* sIn,
                                         int n0, int n, int tid, int seg) {
    for (int i = tid; i < K * 32; i += 256) sW[i] = W[i];
    if (tid < 32) sB[tid] = B[tid];
    for (int i = tid; i < 64 * K; i += 256) {
        int r = i / K, c = i - r * K;
        int row = n0 + r;
        sIn[i] = (row < n) ? in[(long)row * K + c] : 0.f;
    }
    __syncthreads();

    int node = tid >> 2;
    int c0 = (tid & 3) * 8;
    float acc[8];
    #pragma unroll
    for (int j = 0; j < 8; j++) acc[j] = sB[c0 + j];
    const float4* sW4 = (const float4*)sW;
    int wbase = c0 >> 2;
    const float* aIn = sIn + node * K;
    #pragma unroll
    for (int k = 0; k < K; k++) {
        float a = aIn[k];
        float4 w0 = sW4[k * 8 + wbase];
        float4 w1 = sW4[k * 8 + wbase + 1];
        acc[0] += a * w0.x; acc[1] += a * w0.y; acc[2] += a * w0.z; acc[3] += a * w0.w;
        acc[4] += a * w1.x; acc[5] += a * w1.y; acc[6] += a * w1.z; acc[7] += a * w1.w;
    }
    int row = n0 + node;
    if (row < n) {
        float* o = g_bufA + (long)row * 128 + seg * 32 + c0;
        #pragma unroll
        for (int j = 0; j < 8; j++) o[j] = lrelu(acc[j]);
    }
}

__global__ void fuse_small_kernel(const float* __restrict__ nprop, const float* __restrict__ cprop,
                                  const float* __restrict__ Wn, const float* __restrict__ bn,
                                  const float* __restrict__ Wc, const float* __restrict__ bc,
                                  int n) {
    __shared__ __align__(16) float sW[11 * 32];
    __shared__ float sB[32];
    __shared__ __align__(16) float sIn[64 * 11];
    int tid = threadIdx.x;
    int n0 = blockIdx.x * 64;
    if (blockIdx.y == 0) fuse_seg<6> (nprop, Wn, bn, sW, sB, sIn, n0, n, tid, 2);
    else                 fuse_seg<11>(cprop, Wc, bc, sW, sB, sIn, n0, n, tid, 3);
}

// ---------------- mma.sync GEMM (R11 structure; known-good) -----------------
// 512 threads / 16 warps. Warp w: rows (w>>1)*16..+15, cols (w&1)*64..+63.
// mode 0: 1 pass, A = dbuf(selX), weight w0.
// mode 1: 3 passes: p<2 A = g_sums rows (means); p=2 A = dbuf(selX).
// head==1: fused second head layer -> out2[N,2] (no C write).
__global__ __launch_bounds__(512, 1)
void tc_gemm(int mode, int selX, int selC, int w0, int w1, int w2,
             const float* __restrict__ bias, int act, int n,
             const float* __restrict__ Wo2, const float* __restrict__ bo2,
             float* __restrict__ out2, int head) {
    extern __shared__ unsigned char smm[];
    uint32_t sbase = smem_to_u32(smm);
    int tid = threadIdx.x;
    int w = tid >> 5;
    int l = tid & 31;
    int rw = (w >> 1) * 16;
    int cb = (w & 1) * 64;
    int n0 = blockIdx.x * 128;

    float acc[8][4];
    #pragma unroll
    for (int t = 0; t < 8; t++) { acc[t][0] = acc[t][1] = acc[t][2] = acc[t][3] = 0.f; }

    uint32_t aRow = (uint32_t)(rw + (l & 15));
    uint32_t aAddrHi = sbase + OFF_AHI + aRow * SROW + ((uint32_t)(l >> 4)) * 16u;
    uint32_t aAddrLo = aAddrHi + (OFF_ALO - OFF_AHI);
    uint32_t bN = (uint32_t)(cb + (l & 7) + ((l >> 4) << 3));
    uint32_t bAddrHi = sbase + OFF_BHI + bN * SROW + ((uint32_t)((l >> 3) & 1)) * 16u;
    uint32_t bAddrLo = bAddrHi + (OFF_BLO - OFF_BHI);

    int npass = (mode == 1) ? 3 : 1;
    for (int p = 0; p < npass; p++) {
        if (p) __syncthreads();
        // stage B via cp.async (verbatim copy of pre-split bf16 images)
        int widx = (p == 0) ? w0 : (p == 1) ? w1 : w2;
        const uint4* bh = (const uint4*)g_wprep[widx][0];
        const uint4* bl = (const uint4*)g_wprep[widx][1];
        #pragma unroll
        for (int j = 0; j < 4; j++) {
            int i = tid + j * 512;
            uint32_t r = (uint32_t)(i >> 4), c = (uint32_t)(i & 15);
            uint32_t off = r * SROW + c * 16u;
            cp_async16(sbase + OFF_BHI + off, bh + i);
            cp_async16(sbase + OFF_BLO + off, bl + i);
        }
        // stage A: prefetch all global data first (MLP), then convert + STS
        bool from_sums = (mode == 1 && p < 2);
        const float4* X4 = (const float4*)dbuf(selX);
        float4 va[8];
        #pragma unroll
        for (int j = 0; j < 8; j++) {
            int i = tid + j * 512;
            int r = i >> 5, cg = i & 31;
            int row = n0 + r;
            va[j] = make_float4(0.f, 0.f, 0.f, 0.f);
            if (row < n) {
                if (from_sums) {
                    va[j] = ((const float4*)g_sums)[((long)row * 2 + p) * 32 + cg];
                } else {
                    va[j] = X4[(long)row * 32 + cg];
                }
            }
        }
        #pragma unroll
        for (int j = 0; j < 8; j++) {
            int i = tid + j * 512;
            int r = i >> 5, cg = i & 31;
            float x[4] = {va[j].x, va[j].y, va[j].z, va[j].w};
            unsigned short hs[4], ls[4];
            #pragma unroll
            for (int q = 0; q < 4; q++) {
                __nv_bfloat16 h = __float2bfloat16_rn(x[q]);
                float rl = x[q] - __bfloat162float(h);
                __nv_bfloat16 lw = __float2bfloat16_rn(rl);
                hs[q] = __bfloat16_as_ushort(h);
                ls[q] = __bfloat16_as_ushort(lw);
            }
            uint32_t off = (uint32_t)r * SROW + (uint32_t)cg * 8u;
            uint2 uh, ul;
            uh.x = (uint32_t)hs[0] | ((uint32_t)hs[1] << 16);
            uh.y = (uint32_t)hs[2] | ((uint32_t)hs[3] << 16);
            ul.x = (uint32_t)ls[0] | ((uint32_t)ls[1] << 16);
            ul.y = (uint32_t)ls[2] | ((uint32_t)ls[3] << 16);
            *(uint2*)(smm + OFF_AHI + off) = uh;
            *(uint2*)(smm + OFF_ALO + off) = ul;
        }
        cp_async_wait_all();
        __syncthreads();

        // compute: 8 k-steps x 4 n-groups (16 n each, this warp's half) x 3 terms
        for (int k0 = 0; k0 < 8; k0++) {
            uint32_t ah[4], al[4];
            ldsm_x4(ah, aAddrHi + (uint32_t)k0 * 32u);
            ldsm_x4(al, aAddrLo + (uint32_t)k0 * 32u);
            #pragma unroll
            for (int ng = 0; ng < 4; ng++) {
                uint32_t bhf[4], blf[4];
                uint32_t boff = (uint32_t)ng * (16u * SROW) + (uint32_t)k0 * 32u;
                ldsm_x4(bhf, bAddrHi + boff);   // non-trans: [n][k] is already col-major
                ldsm_x4(blf, bAddrLo + boff);
                mma_bf16(acc[2 * ng],     ah, bhf[0], bhf[1]);
                mma_bf16(acc[2 * ng],     ah, blf[0], blf[1]);
                mma_bf16(acc[2 * ng],     al, bhf[0], bhf[1]);
                mma_bf16(acc[2 * ng + 1], ah, bhf[2], bhf[3]);
                mma_bf16(acc[2 * ng + 1], ah, blf[2], blf[3]);
                mma_bf16(acc[2 * ng + 1], al, bhf[2], bhf[3]);
            }
        }
    }

    if (head) {
        // fused head: out2[row] = lrelu(acc+bias) @ Wo2 + bo2
        float p00 = 0.f, p01 = 0.f, p10 = 0.f, p11 = 0.f;
        #pragma unroll
        for (int t = 0; t < 8; t++) {
            int col = cb + t * 8 + (l & 3) * 2;
            float b0 = bias[col], b1 = bias[col + 1];
            float w00 = Wo2[col * 2], w01 = Wo2[col * 2 + 1];
            float w10 = Wo2[(col + 1) * 2], w11 = Wo2[(col + 1) * 2 + 1];
            float o0 = lrelu(acc[t][0] + b0), o1 = lrelu(acc[t][1] + b1);
            p00 += o0 * w00 + o1 * w10;  p01 += o0 * w01 + o1 * w11;
            float o2 = lrelu(acc[t][2] + b0), o3 = lrelu(acc[t][3] + b1);
            p10 += o2 * w00 + o3 * w10;  p11 += o2 * w01 + o3 * w11;
        }
        #pragma unroll
        for (int m = 1; m <= 2; m <<= 1) {
            p00 += __shfl_xor_sync(0xFFFFFFFFu, p00, m);
            p01 += __shfl_xor_sync(0xFFFFFFFFu, p01, m);
            p10 += __shfl_xor_sync(0xFFFFFFFFu, p10, m);
            p11 += __shfl_xor_sync(0xFFFFFFFFu, p11, m);
        }
        __syncthreads();
        float* scratch = (float*)(smm + OFF_BHI);
        int rr0 = rw + (l >> 2);
        if ((w & 1) == 0 && (l & 3) == 0) {
            scratch[rr0 * 2 + 0] = p00;  scratch[rr0 * 2 + 1] = p01;
            scratch[(rr0 + 8) * 2 + 0] = p10;  scratch[(rr0 + 8) * 2 + 1] = p11;
        }
        __syncthreads();
        if ((w & 1) == 1 && (l & 3) == 0) {
            int row0 = n0 + rr0, row1 = row0 + 8;
            float c0 = bo2[0], c1 = bo2[1];
            if (row0 < n) {
                out2[row0 * 2 + 0] = scratch[rr0 * 2 + 0] + p00 + c0;
                out2[row0 * 2 + 1] = scratch[rr0 * 2 + 1] + p01 + c1;
            }
            if (row1 < n) {
                out2[row1 * 2 + 0] = scratch[(rr0 + 8) * 2 + 0] + p10 + c0;
                out2[row1 * 2 + 1] = scratch[(rr0 + 8) * 2 + 1] + p11 + c1;
            }
        }
        return;
    }

    float* C = dbuf(selC);
    int r0 = n0 + rw + (l >> 2);
    int r1 = r0 + 8;
    #pragma unroll
    for (int t = 0; t < 8; t++) {
        int col = cb + t * 8 + (l & 3) * 2;
        float b0 = bias[col], b1 = bias[col + 1];
        if (r0 < n) {
            float2 o;
            o.x = acc[t][0] + b0; o.y = acc[t][1] + b1;
            if (act) { o.x = lrelu(o.x); o.y = lrelu(o.y); }
            *(float2*)(C + (long)r0 * 128 + col) = o;
        }
        if (r1 < n) {
            float2 o;
            o.x = acc[t][2] + b0; o.y = acc[t][3] + b1;
            if (act) { o.x = lrelu(o.x); o.y = lrelu(o.y); }
            *(float2*)(C + (long)r1 * 128 + col) = o;
        }
    }
}

// ---------------- host ------------------------------------------------------
extern "C" void kernel_launch(void* const* d_in, const int* in_sizes, int n_in,
                              void* d_out, int out_size) {
    const float* des  = (const float*)d_in[0];
    const float* tw   = (const float*)d_in[1];
    const float* npr  = (const float*)d_in[2];
    const float* cpr  = (const float*)d_in[3];
    const void*  ei   = d_in[4];
    const void*  et   = d_in[5];
    const float* Wd   = (const float*)d_in[6];  const float* bd  = (const float*)d_in[7];
    const float* Wt   = (const float*)d_in[8];  const float* bt  = (const float*)d_in[9];
    const float* Wn   = (const float*)d_in[10]; const float* bn  = (const float*)d_in[11];
    const float* Wc   = (const float*)d_in[12]; const float* bc  = (const float*)d_in[13];
    const float* Win  = (const float*)d_in[14]; const float* bin = (const float*)d_in[15];
    const float* Wrel = (const float*)d_in[16];
    const float* Wroot= (const float*)d_in[17];
    const float* brg  = (const float*)d_in[18];
    const float* Wo1  = (const float*)d_in[19]; const float* bo1 = (const float*)d_in[20];
    const float* Wo2  = (const float*)d_in[21]; const float* bo2 = (const float*)d_in[22];
    float* out = (float*)d_out;

    int N = in_sizes[0] / 100;
    int E = in_sizes[5];
    int n2 = 2 * N;
    int nb_scan = (n2 + SCAN_B - 1) / SCAN_B;

    const int FUSE_SMEM = (3200 + 12800 + 32) * 4;   // 64128 B
    cudaFuncSetAttribute(tc_gemm, cudaFuncAttributeMaxDynamicSharedMemorySize, TC_SMEM);
    cudaFuncSetAttribute(fuse100_kernel, cudaFuncAttributeMaxDynamicSharedMemorySize, FUSE_SMEM);

    int nb64 = (N + 63) / 64;
    int nb128 = (N + 127) / 128;
    int eb = (E + 255) / 256;

    detect_kernel<<<(n2 + 255) / 256, 256>>>((const int*)ei, n2);
    wprep_kernel<<<5, 256>>>(Win, Wrel, Wroot, Wo1);

    // CSR build (once; reused by both layers)
    icount_kernel<<<eb, 256>>>(ei, et, E);
    scan_block_sums<<<nb_scan, 256>>>(n2);
    scan_tops<<<1, 256>>>(nb_scan);
    scan_offsets<<<nb_scan, 256>>>(n2);
    fill_kernel<<<eb, 256>>>(ei, et, E);

    fuse100_kernel<<<dim3(nb128, 2), 256, FUSE_SMEM>>>(des, tw, Wd, bd, Wt, bt, N);
    fuse_small_kernel<<<dim3(nb64, 2), 256>>>(npr, cpr, Wn, bn, Wc, bc, N);
    tc_gemm<<<nb128, 512, TC_SMEM>>>(0, 0, 1, 0, 0, 0, bin, 1, N, 0, 0, 0, 0);  // bufA -> bufB

    mean_kernel<<<(n2 + 7) / 8, 256>>>(1, n2);                                   // x0 means
    tc_gemm<<<nb128, 512, TC_SMEM>>>(1, 1, 2, 1, 2, 3, brg, 0, N, 0, 0, 0, 0);  // -> bufC

    mean_kernel<<<(n2 + 7) / 8, 256>>>(2, n2);                                   // x1 means
    tc_gemm<<<nb128, 512, TC_SMEM>>>(1, 2, 0, 1, 2, 3, brg, 0, N, 0, 0, 0, 0);  // -> bufA

    // head: GEMM(Wo1)+lrelu fused with @Wo2+b2 -> out
    tc_gemm<<<nb128, 512, TC_SMEM>>>(0, 0, 1, 4, 0, 0, bo1, 1, N, Wo2, bo2, out, 1);
}

// round 15
// speedup vs baseline: 1.0820x; 1.0393x over previous
#include <cuda_runtime.h>
#include <cuda_bf16.h>
#include <cstdint>

#define MAXN 100000
#define MAXE 1600000
#define SCAN_B 1024
#define MAXSEG (2 * MAXN)

// ---------------- scratch (device globals; no runtime allocation) ----------
__device__ float g_bufA[MAXN * 128];        // 51.2 MB
__device__ float g_bufB[MAXN * 128];        // 51.2 MB
__device__ float g_bufC[MAXN * 128];        // 51.2 MB
__device__ float g_sums[MAXSEG * 128];      // 102.4 MB  per-(node,rel) means
__device__ int   g_flag[1];                 // 1 => indices are int64
// CSR over (dst,rel) segments
__device__ int   g_icnt[MAXSEG];
__device__ int   g_off[MAXSEG];
__device__ int   g_fill[MAXSEG];
__device__ int   g_bsum[256];
__device__ int   g_boff[256];
__device__ int   g_srcs[MAXE];
// pre-split, pre-transposed weights Bt[n][k], row-major bf16: [widx][hi/lo][32KB]
__device__ __align__(16) unsigned char g_wprep[5][2][32768];

__device__ __forceinline__ float* dbuf(int s) {
    return (s == 0) ? g_bufA : (s == 1) ? g_bufB : g_bufC;
}
__device__ __forceinline__ float lrelu(float v) { return v > 0.f ? v : 0.01f * v; }

// ---------------- mma.sync / cp.async helpers (sm_80+) ----------------------
__device__ __forceinline__ void ldsm_x4(uint32_t* r, uint32_t addr) {
    asm volatile("ldmatrix.sync.aligned.m8n8.x4.shared.b16 {%0,%1,%2,%3}, [%4];"
                 : "=r"(r[0]), "=r"(r[1]), "=r"(r[2]), "=r"(r[3]) : "r"(addr));
}
__device__ __forceinline__ void mma_bf16(float* c, const uint32_t* a, uint32_t b0, uint32_t b1) {
    asm volatile("mma.sync.aligned.m16n8k16.row.col.f32.bf16.bf16.f32 "
                 "{%0,%1,%2,%3}, {%4,%5,%6,%7}, {%8,%9}, {%0,%1,%2,%3};"
                 : "+f"(c[0]), "+f"(c[1]), "+f"(c[2]), "+f"(c[3])
                 : "r"(a[0]), "r"(a[1]), "r"(a[2]), "r"(a[3]), "r"(b0), "r"(b1));
}
__device__ __forceinline__ uint32_t smem_to_u32(const void* p) {
    uint32_t a;
    asm("{ .reg .u64 t; cvta.to.shared.u64 t, %1; cvt.u32.u64 %0, t; }" : "=r"(a) : "l"(p));
    return a;
}
__device__ __forceinline__ void cp_async16(uint32_t smem_addr, const void* gptr) {
    size_t ga = __cvta_generic_to_global((void*)gptr);
    asm volatile("cp.async.cg.shared.global [%0], [%1], 16;"
                 :: "r"(smem_addr), "l"(ga) : "memory");
}
__device__ __forceinline__ void cp_async_wait_all() {
    asm volatile("cp.async.commit_group;\ncp.async.wait_group 0;" ::: "memory");
}

// SMEM tile geometry: rows of 136 bf16 (stride 272 B -> ldmatrix conflict-free)
// A tile: 64 rows; B tile: 128 n-rows. 2 CTAs/SM.
#define SROW 272
#define ABUF (64 * SROW)           // 17408 B per A image
#define BBUF (128 * SROW)          // 34816 B per B image
#define OFF_AHI 0
#define OFF_ALO (ABUF)
#define OFF_BHI (2 * ABUF)
#define OFF_BLO (2 * ABUF + BBUF)
#define TC_SMEM (2 * ABUF + 2 * BBUF)   // 104448 B

// ---------------- dtype detection + CSR zeroing -----------------------------
__global__ void detect_kernel(const int* __restrict__ ei, int n2) {
    __shared__ int s_nz;
    if (blockIdx.x == 0) {
        if (threadIdx.x == 0) s_nz = 0;
        __syncthreads();
        for (int p = threadIdx.x; p < 1024; p += blockDim.x)
            if (ei[2 * p + 1] != 0) s_nz = 1;
        __syncthreads();
        if (threadIdx.x == 0) g_flag[0] = (s_nz == 0) ? 1 : 0;
    }
    int i = blockIdx.x * 256 + threadIdx.x;
    if (i < n2) { g_icnt[i] = 0; g_fill[i] = 0; }
}

// ---------------- CSR build --------------------------------------------------
__global__ void icount_kernel(const void* __restrict__ ei, const void* __restrict__ et, int E) {
    int e = blockIdx.x * 256 + threadIdx.x;
    if (e >= E) return;
    long dst, typ;
    if (g_flag[0]) {
        dst = ((const long long*)ei)[(long)E + e];
        typ = ((const long long*)et)[e];
    } else {
        dst = ((const int*)ei)[E + e];
        typ = ((const int*)et)[e];
    }
    atomicAdd(&g_icnt[dst * 2 + typ], 1);
}

__global__ void scan_block_sums(int n2) {
    __shared__ int ssum[256];
    int base = blockIdx.x * SCAN_B;
    int tsum = 0;
    for (int i = threadIdx.x; i < SCAN_B; i += 256) {
        int idx = base + i;
        tsum += (idx < n2) ? g_icnt[idx] : 0;
    }
    ssum[threadIdx.x] = tsum;
    __syncthreads();
    for (int s = 128; s > 0; s >>= 1) {
        if (threadIdx.x < s) ssum[threadIdx.x] += ssum[threadIdx.x + s];
        __syncthreads();
    }
    if (threadIdx.x == 0) g_bsum[blockIdx.x] = ssum[0];
}

__global__ void scan_tops(int nb) {
    __shared__ int sv[256];
    int t = threadIdx.x;
    sv[t] = (t < nb) ? g_bsum[t] : 0;
    __syncthreads();
    if (t == 0) {
        int run = 0;
        for (int i = 0; i < nb; i++) { int c = sv[i]; sv[i] = run; run += c; }
    }
    __syncthreads();
    if (t < nb) g_boff[t] = sv[t];
}

__global__ void scan_offsets(int n2) {
    __shared__ int warpsum[8];
    int t = threadIdx.x;
    int base = blockIdx.x * SCAN_B + t * 4;
    int v[4];
    #pragma unroll
    for (int j = 0; j < 4; j++) v[j] = (base + j < n2) ? g_icnt[base + j] : 0;
    int tsum = v[0] + v[1] + v[2] + v[3];
    int lane = t & 31, wid = t >> 5;
    int x = tsum;
    #pragma unroll
    for (int o = 1; o < 32; o <<= 1) {
        int y = __shfl_up_sync(0xFFFFFFFFu, x, o);
        if (lane >= o) x += y;
    }
    if (lane == 31) warpsum[wid] = x;
    __syncthreads();
    if (t == 0) {
        int run = 0;
        for (int i = 0; i < 8; i++) { int c = warpsum[i]; warpsum[i] = run; run += c; }
    }
    __syncthreads();
    int ex = x - tsum + warpsum[wid] + g_boff[blockIdx.x];
    #pragma unroll
    for (int j = 0; j < 4; j++) {
        if (base + j < n2) g_off[base + j] = ex;
        ex += v[j];
    }
}

__global__ void fill_kernel(const void* __restrict__ ei, const void* __restrict__ et, int E) {
    int e = blockIdx.x * 256 + threadIdx.x;
    if (e >= E) return;
    long src, dst, typ;
    if (g_flag[0]) {
        const long long* p = (const long long*)ei;
        src = p[e]; dst = p[(long)E + e];
        typ = ((const long long*)et)[e];
    } else {
        const int* p = (const int*)ei;
        src = p[e]; dst = p[E + e];
        typ = ((const int*)et)[e];
    }
    int s = (int)(dst * 2 + typ);
    int pos = atomicAdd(&g_fill[s], 1);
    g_srcs[g_off[s] + pos] = (int)src;
}

// ---------------- mean aggregation: warp per (dst,rel) segment --------------
__global__ void mean_kernel(int selX, int n2) {
    int seg = blockIdx.x * 8 + (threadIdx.x >> 5);
    int lane = threadIdx.x & 31;
    if (seg >= n2) return;
    int deg = g_icnt[seg];
    int base = g_off[seg];
    const float4* X4 = (const float4*)dbuf(selX);
    float4 acc = make_float4(0.f, 0.f, 0.f, 0.f);
    int i = 0;
    for (; i + 4 <= deg; i += 4) {
        int s0 = g_srcs[base + i], s1 = g_srcs[base + i + 1];
        int s2 = g_srcs[base + i + 2], s3 = g_srcs[base + i + 3];
        float4 v0 = X4[(long)s0 * 32 + lane];
        float4 v1 = X4[(long)s1 * 32 + lane];
        float4 v2 = X4[(long)s2 * 32 + lane];
        float4 v3 = X4[(long)s3 * 32 + lane];
        acc.x += v0.x + v1.x + v2.x + v3.x;
        acc.y += v0.y + v1.y + v2.y + v3.y;
        acc.z += v0.z + v1.z + v2.z + v3.z;
        acc.w += v0.w + v1.w + v2.w + v3.w;
    }
    for (; i < deg; i++) {
        int s0 = g_srcs[base + i];
        float4 v0 = X4[(long)s0 * 32 + lane];
        acc.x += v0.x; acc.y += v0.y; acc.z += v0.z; acc.w += v0.w;
    }
    float sc = 1.0f / (float)max(deg, 1);
    acc.x *= sc; acc.y *= sc; acc.z *= sc; acc.w *= sc;
    ((float4*)g_sums)[(long)seg * 32 + lane] = acc;
}

// ---------------- weight prep: W[128,128] -> Bt[n][k] bf16 hi/lo ------------
__global__ void wprep_kernel(const float* __restrict__ Win, const float* __restrict__ Wrel,
                             const float* __restrict__ Wroot, const float* __restrict__ Wo1) {
    int w = blockIdx.x;
    const float* W = (w == 0) ? Win : (w == 1) ? Wrel : (w == 2) ? (Wrel + 16384)
                   : (w == 3) ? Wroot : Wo1;
    unsigned char* hi = g_wprep[w][0];
    unsigned char* lo = g_wprep[w][1];
    for (int i = threadIdx.x; i < 4096; i += blockDim.x) {
        int nrow = i >> 5;
        int k0 = (i & 31) * 4;
        unsigned short hs[4], ls[4];
        #pragma unroll
        for (int j = 0; j < 4; j++) {
            float x = W[(k0 + j) * 128 + nrow];   // Bt[n][k] = W[k][n]
            __nv_bfloat16 h = __float2bfloat16_rn(x);
            float rl = x - __bfloat162float(h);
            __nv_bfloat16 l = __float2bfloat16_rn(rl);
            hs[j] = __bfloat16_as_ushort(h);
            ls[j] = __bfloat16_as_ushort(l);
        }
        uint32_t off = (uint32_t)nrow * 256u + (uint32_t)k0 * 2u;
        uint2 uh, ul;
        uh.x = (uint32_t)hs[0] | ((uint32_t)hs[1] << 16);
        uh.y = (uint32_t)hs[2] | ((uint32_t)hs[3] << 16);
        ul.x = (uint32_t)ls[0] | ((uint32_t)ls[1] << 16);
        ul.y = (uint32_t)ls[2] | ((uint32_t)ls[3] << 16);
        *(uint2*)(hi + off) = uh;
        *(uint2*)(lo + off) = ul;
    }
}

// ---------------- feature fusion: K=100 register-blocked kernel -------------
__global__ void fuse100_kernel(const float* __restrict__ des, const float* __restrict__ tw,
                               const float* __restrict__ Wd, const float* __restrict__ bd,
                               const float* __restrict__ Wt, const float* __restrict__ bt,
                               int n) {
    extern __shared__ float fsm[];
    float* sW = fsm;                 // 100*32 = 3200
    float* sIn = fsm + 3200;         // 128*100 = 12800
    float* sB = fsm + 3200 + 12800;  // 32
    int tid = threadIdx.x;
    int n0 = blockIdx.x * 128;
    int seg = blockIdx.y;
    const float* in = seg ? tw : des;
    const float* W = seg ? Wt : Wd;
    const float* B = seg ? bt : bd;

    for (int i = tid; i < 3200; i += 256) sW[i] = W[i];
    if (tid < 32) sB[tid] = B[tid];
    const float4* in4 = (const float4*)in;
    float4* sIn4 = (float4*)sIn;
    for (int i = tid; i < 128 * 25; i += 256) {
        int r = i / 25, c = i - r * 25;
        int row = n0 + r;
        sIn4[i] = (row < n) ? in4[(long)row * 25 + c] : make_float4(0.f, 0.f, 0.f, 0.f);
    }
    __syncthreads();

    int ng = tid >> 3;
    int cg = tid & 7;
    int c0 = cg * 4;
    float acc[4][4];
    #pragma unroll
    for (int j = 0; j < 4; j++) {
        acc[j][0] = sB[c0]; acc[j][1] = sB[c0 + 1];
        acc[j][2] = sB[c0 + 2]; acc[j][3] = sB[c0 + 3];
    }
    const float4* sW4 = (const float4*)sW;
    const float* a0 = sIn + (ng * 4 + 0) * 100;
    const float* a1 = sIn + (ng * 4 + 1) * 100;
    const float* a2 = sIn + (ng * 4 + 2) * 100;
    const float* a3 = sIn + (ng * 4 + 3) * 100;
    #pragma unroll 4
    for (int k = 0; k < 100; k++) {
        float4 wv = sW4[k * 8 + cg];
        float x0 = a0[k], x1 = a1[k], x2 = a2[k], x3 = a3[k];
        acc[0][0] += x0 * wv.x; acc[0][1] += x0 * wv.y; acc[0][2] += x0 * wv.z; acc[0][3] += x0 * wv.w;
        acc[1][0] += x1 * wv.x; acc[1][1] += x1 * wv.y; acc[1][2] += x1 * wv.z; acc[1][3] += x1 * wv.w;
        acc[2][0] += x2 * wv.x; acc[2][1] += x2 * wv.y; acc[2][2] += x2 * wv.z; acc[2][3] += x2 * wv.w;
        acc[3][0] += x3 * wv.x; acc[3][1] += x3 * wv.y; acc[3][2] += x3 * wv.z; acc[3][3] += x3 * wv.w;
    }
    #pragma unroll
    for (int j = 0; j < 4; j++) {
        int row = n0 + ng * 4 + j;
        if (row < n) {
            float4 o;
            o.x = lrelu(acc[j][0]); o.y = lrelu(acc[j][1]);
            o.z = lrelu(acc[j][2]); o.w = lrelu(acc[j][3]);
            *(float4*)(g_bufA + (long)row * 128 + seg * 32 + c0) = o;
        }
    }
}

// ---------------- feature fusion: small K (6, 11) ---------------------------
template<int K>
__device__ __forceinline__ void fuse_seg(const float* __restrict__ in,
                                         const float* __restrict__ W,
                                         const float* __restrict__ B,
                                         float* sW, float* sB, float* sIn,
                                         int n0, int n, int tid, int seg) {
    for (int i = tid; i < K * 32; i += 256) sW[i] = W[i];
    if (tid < 32) sB[tid] = B[tid];
    for (int i = tid; i < 64 * K; i += 256) {
        int r = i / K, c = i - r * K;
        int row = n0 + r;
        sIn[i] = (row < n) ? in[(long)row * K + c] : 0.f;
    }
    __syncthreads();

    int node = tid >> 2;
    int c0 = (tid & 3) * 8;
    float acc[8];
    #pragma unroll
    for (int j = 0; j < 8; j++) acc[j] = sB[c0 + j];
    const float4* sW4 = (const float4*)sW;
    int wbase = c0 >> 2;
    const float* aIn = sIn + node * K;
    #pragma unroll
    for (int k = 0; k < K; k++) {
        float a = aIn[k];
        float4 w0 = sW4[k * 8 + wbase];
        float4 w1 = sW4[k * 8 + wbase + 1];
        acc[0] += a * w0.x; acc[1] += a * w0.y; acc[2] += a * w0.z; acc[3] += a * w0.w;
        acc[4] += a * w1.x; acc[5] += a * w1.y; acc[6] += a * w1.z; acc[7] += a * w1.w;
    }
    int row = n0 + node;
    if (row < n) {
        float* o = g_bufA + (long)row * 128 + seg * 32 + c0;
        #pragma unroll
        for (int j = 0; j < 8; j++) o[j] = lrelu(acc[j]);
    }
}

__global__ void fuse_small_kernel(const float* __restrict__ nprop, const float* __restrict__ cprop,
                                  const float* __restrict__ Wn, const float* __restrict__ bn,
                                  const float* __restrict__ Wc, const float* __restrict__ bc,
                                  int n) {
    __shared__ __align__(16) float sW[11 * 32];
    __shared__ float sB[32];
    __shared__ __align__(16) float sIn[64 * 11];
    int tid = threadIdx.x;
    int n0 = blockIdx.x * 64;
    if (blockIdx.y == 0) fuse_seg<6> (nprop, Wn, bn, sW, sB, sIn, n0, n, tid, 2);
    else                 fuse_seg<11>(cprop, Wc, bc, sW, sB, sIn, n0, n, tid, 3);
}

// ---------------- mma.sync GEMM: 64-row tiles, 256 thr, 2 CTAs/SM -----------
// 8 warps. Warp w: rows (w>>1)*16..+15, cols (w&1)*64..+63.
// mode 0: 1 pass, A = dbuf(selX), weight w0.
// mode 1: 3 passes: p<2 A = g_sums rows (means); p=2 A = dbuf(selX).
// head==1: fused second head layer -> out2[N,2] (no C write).
__global__ __launch_bounds__(256, 2)
void tc_gemm(int mode, int selX, int selC, int w0, int w1, int w2,
             const float* __restrict__ bias, int act, int n,
             const float* __restrict__ Wo2, const float* __restrict__ bo2,
             float* __restrict__ out2, int head) {
    extern __shared__ unsigned char smm[];
    uint32_t sbase = smem_to_u32(smm);
    int tid = threadIdx.x;
    int w = tid >> 5;
    int l = tid & 31;
    int rw = (w >> 1) * 16;        // row base within 64-row tile
    int cb = (w & 1) * 64;         // col base
    int n0 = blockIdx.x * 64;

    float acc[8][4];
    #pragma unroll
    for (int t = 0; t < 8; t++) { acc[t][0] = acc[t][1] = acc[t][2] = acc[t][3] = 0.f; }

    uint32_t aRow = (uint32_t)(rw + (l & 15));
    uint32_t aAddrHi = sbase + OFF_AHI + aRow * SROW + ((uint32_t)(l >> 4)) * 16u;
    uint32_t aAddrLo = aAddrHi + (OFF_ALO - OFF_AHI);
    uint32_t bN = (uint32_t)(cb + (l & 7) + ((l >> 4) << 3));
    uint32_t bAddrHi = sbase + OFF_BHI + bN * SROW + ((uint32_t)((l >> 3) & 1)) * 16u;
    uint32_t bAddrLo = bAddrHi + (OFF_BLO - OFF_BHI);

    int npass = (mode == 1) ? 3 : 1;
    for (int p = 0; p < npass; p++) {
        if (p) __syncthreads();
        // stage B via cp.async (verbatim copy of pre-split bf16 images)
        int widx = (p == 0) ? w0 : (p == 1) ? w1 : w2;
        const uint4* bh = (const uint4*)g_wprep[widx][0];
        const uint4* bl = (const uint4*)g_wprep[widx][1];
        #pragma unroll
        for (int j = 0; j < 8; j++) {
            int i = tid + j * 256;
            uint32_t r = (uint32_t)(i >> 4), c = (uint32_t)(i & 15);
            uint32_t off = r * SROW + c * 16u;
            cp_async16(sbase + OFF_BHI + off, bh + i);
            cp_async16(sbase + OFF_BLO + off, bl + i);
        }
        // stage A: prefetch all global data first (MLP), then convert + STS
        bool from_sums = (mode == 1 && p < 2);
        const float4* X4 = (const float4*)dbuf(selX);
        float4 va[8];
        #pragma unroll
        for (int j = 0; j < 8; j++) {
            int i = tid + j * 256;
            int r = i >> 5, cg = i & 31;
            int row = n0 + r;
            va[j] = make_float4(0.f, 0.f, 0.f, 0.f);
            if (row < n) {
                if (from_sums) {
                    va[j] = ((const float4*)g_sums)[((long)row * 2 + p) * 32 + cg];
                } else {
                    va[j] = X4[(long)row * 32 + cg];
                }
            }
        }
        #pragma unroll
        for (int j = 0; j < 8; j++) {
            int i = tid + j * 256;
            int r = i >> 5, cg = i & 31;
            float x[4] = {va[j].x, va[j].y, va[j].z, va[j].w};
            unsigned short hs[4], ls[4];
            #pragma unroll
            for (int q = 0; q < 4; q++) {
                __nv_bfloat16 h = __float2bfloat16_rn(x[q]);
                float rl = x[q] - __bfloat162float(h);
                __nv_bfloat16 lw = __float2bfloat16_rn(rl);
                hs[q] = __bfloat16_as_ushort(h);
                ls[q] = __bfloat16_as_ushort(lw);
            }
            uint32_t off = (uint32_t)r * SROW + (uint32_t)cg * 8u;
            uint2 uh, ul;
            uh.x = (uint32_t)hs[0] | ((uint32_t)hs[1] << 16);
            uh.y = (uint32_t)hs[2] | ((uint32_t)hs[3] << 16);
            ul.x = (uint32_t)ls[0] | ((uint32_t)ls[1] << 16);
            ul.y = (uint32_t)ls[2] | ((uint32_t)ls[3] << 16);
            *(uint2*)(smm + OFF_AHI + off) = uh;
            *(uint2*)(smm + OFF_ALO + off) = ul;
        }
        cp_async_wait_all();
        __syncthreads();

        // compute: 8 k-steps x 4 n-groups (16 n each, this warp's half) x 3 terms
        for (int k0 = 0; k0 < 8; k0++) {
            uint32_t ah[4], al[4];
            ldsm_x4(ah, aAddrHi + (uint32_t)k0 * 32u);
            ldsm_x4(al, aAddrLo + (uint32_t)k0 * 32u);
            #pragma unroll
            for (int ng = 0; ng < 4; ng++) {
                uint32_t bhf[4], blf[4];
                uint32_t boff = (uint32_t)ng * (16u * SROW) + (uint32_t)k0 * 32u;
                ldsm_x4(bhf, bAddrHi + boff);   // non-trans: [n][k] is already col-major
                ldsm_x4(blf, bAddrLo + boff);
                mma_bf16(acc[2 * ng],     ah, bhf[0], bhf[1]);
                mma_bf16(acc[2 * ng],     ah, blf[0], blf[1]);
                mma_bf16(acc[2 * ng],     al, bhf[0], bhf[1]);
                mma_bf16(acc[2 * ng + 1], ah, bhf[2], bhf[3]);
                mma_bf16(acc[2 * ng + 1], ah, blf[2], blf[3]);
                mma_bf16(acc[2 * ng + 1], al, bhf[2], bhf[3]);
            }
        }
    }

    if (head) {
        // fused head: out2[row] = lrelu(acc+bias) @ Wo2 + bo2
        float p00 = 0.f, p01 = 0.f, p10 = 0.f, p11 = 0.f;
        #pragma unroll
        for (int t = 0; t < 8; t++) {
            int col = cb + t * 8 + (l & 3) * 2;
            float b0 = bias[col], b1 = bias[col + 1];
            float w00 = Wo2[col * 2], w01 = Wo2[col * 2 + 1];
            float w10 = Wo2[(col + 1) * 2], w11 = Wo2[(col + 1) * 2 + 1];
            float o0 = lrelu(acc[t][0] + b0), o1 = lrelu(acc[t][1] + b1);
            p00 += o0 * w00 + o1 * w10;  p01 += o0 * w01 + o1 * w11;
            float o2 = lrelu(acc[t][2] + b0), o3 = lrelu(acc[t][3] + b1);
            p10 += o2 * w00 + o3 * w10;  p11 += o2 * w01 + o3 * w11;
        }
        #pragma unroll
        for (int m = 1; m <= 2; m <<= 1) {
            p00 += __shfl_xor_sync(0xFFFFFFFFu, p00, m);
            p01 += __shfl_xor_sync(0xFFFFFFFFu, p01, m);
            p10 += __shfl_xor_sync(0xFFFFFFFFu, p10, m);
            p11 += __shfl_xor_sync(0xFFFFFFFFu, p11, m);
        }
        __syncthreads();
        float* scratch = (float*)(smm + OFF_BHI);   // 64 rows x 2 floats
        int rr0 = rw + (l >> 2);
        if ((w & 1) == 0 && (l & 3) == 0) {
            scratch[rr0 * 2 + 0] = p00;  scratch[rr0 * 2 + 1] = p01;
            scratch[(rr0 + 8) * 2 + 0] = p10;  scratch[(rr0 + 8) * 2 + 1] = p11;
        }
        __syncthreads();
        if ((w & 1) == 1 && (l & 3) == 0) {
            int row0 = n0 + rr0, row1 = row0 + 8;
            float c0 = bo2[0], c1 = bo2[1];
            if (row0 < n) {
                out2[row0 * 2 + 0] = scratch[rr0 * 2 + 0] + p00 + c0;
                out2[row0 * 2 + 1] = scratch[rr0 * 2 + 1] + p01 + c1;
            }
            if (row1 < n) {
                out2[row1 * 2 + 0] = scratch[(rr0 + 8) * 2 + 0] + p10 + c0;
                out2[row1 * 2 + 1] = scratch[(rr0 + 8) * 2 + 1] + p11 + c1;
            }
        }
        return;
    }

    float* C = dbuf(selC);
    int r0 = n0 + rw + (l >> 2);
    int r1 = r0 + 8;
    #pragma unroll
    for (int t = 0; t < 8; t++) {
        int col = cb + t * 8 + (l & 3) * 2;
        float b0 = bias[col], b1 = bias[col + 1];
        if (r0 < n) {
            float2 o;
            o.x = acc[t][0] + b0; o.y = acc[t][1] + b1;
            if (act) { o.x = lrelu(o.x); o.y = lrelu(o.y); }
            *(float2*)(C + (long)r0 * 128 + col) = o;
        }
        if (r1 < n) {
            float2 o;
            o.x = acc[t][2] + b0; o.y = acc[t][3] + b1;
            if (act) { o.x = lrelu(o.x); o.y = lrelu(o.y); }
            *(float2*)(C + (long)r1 * 128 + col) = o;
        }
    }
}

// ---------------- host ------------------------------------------------------
extern "C" void kernel_launch(void* const* d_in, const int* in_sizes, int n_in,
                              void* d_out, int out_size) {
    const float* des  = (const float*)d_in[0];
    const float* tw   = (const float*)d_in[1];
    const float* npr  = (const float*)d_in[2];
    const float* cpr  = (const float*)d_in[3];
    const void*  ei   = d_in[4];
    const void*  et   = d_in[5];
    const float* Wd   = (const float*)d_in[6];  const float* bd  = (const float*)d_in[7];
    const float* Wt   = (const float*)d_in[8];  const float* bt  = (const float*)d_in[9];
    const float* Wn   = (const float*)d_in[10]; const float* bn  = (const float*)d_in[11];
    const float* Wc   = (const float*)d_in[12]; const float* bc  = (const float*)d_in[13];
    const float* Win  = (const float*)d_in[14]; const float* bin = (const float*)d_in[15];
    const float* Wrel = (const float*)d_in[16];
    const float* Wroot= (const float*)d_in[17];
    const float* brg  = (const float*)d_in[18];
    const float* Wo1  = (const float*)d_in[19]; const float* bo1 = (const float*)d_in[20];
    const float* Wo2  = (const float*)d_in[21]; const float* bo2 = (const float*)d_in[22];
    float* out = (float*)d_out;

    int N = in_sizes[0] / 100;
    int E = in_sizes[5];
    int n2 = 2 * N;
    int nb_scan = (n2 + SCAN_B - 1) / SCAN_B;

    const int FUSE_SMEM = (3200 + 12800 + 32) * 4;   // 64128 B
    cudaFuncSetAttribute(tc_gemm, cudaFuncAttributeMaxDynamicSharedMemorySize, TC_SMEM);
    cudaFuncSetAttribute(fuse100_kernel, cudaFuncAttributeMaxDynamicSharedMemorySize, FUSE_SMEM);

    int nb64 = (N + 63) / 64;
    int nb128 = (N + 127) / 128;
    int eb = (E + 255) / 256;

    detect_kernel<<<(n2 + 255) / 256, 256>>>((const int*)ei, n2);
    wprep_kernel<<<5, 256>>>(Win, Wrel, Wroot, Wo1);

    // CSR build (once; reused by both layers)
    icount_kernel<<<eb, 256>>>(ei, et, E);
    scan_block_sums<<<nb_scan, 256>>>(n2);
    scan_tops<<<1, 256>>>(nb_scan);
    scan_offsets<<<nb_scan, 256>>>(n2);
    fill_kernel<<<eb, 256>>>(ei, et, E);

    fuse100_kernel<<<dim3(nb128, 2), 256, FUSE_SMEM>>>(des, tw, Wd, bd, Wt, bt, N);
    fuse_small_kernel<<<dim3(nb64, 2), 256>>>(npr, cpr, Wn, bn, Wc, bc, N);
    tc_gemm<<<nb64, 256, TC_SMEM>>>(0, 0, 1, 0, 0, 0, bin, 1, N, 0, 0, 0, 0);  // bufA -> bufB

    mean_kernel<<<(n2 + 7) / 8, 256>>>(1, n2);                                  // x0 means
    tc_gemm<<<nb64, 256, TC_SMEM>>>(1, 1, 2, 1, 2, 3, brg, 0, N, 0, 0, 0, 0);  // -> bufC

    mean_kernel<<<(n2 + 7) / 8, 256>>>(2, n2);                                  // x1 means
    tc_gemm<<<nb64, 256, TC_SMEM>>>(1, 2, 0, 1, 2, 3, brg, 0, N, 0, 0, 0, 0);  // -> bufA

    // head: GEMM(Wo1)+lrelu fused with @Wo2+b2 -> out
    tc_gemm<<<nb64, 256, TC_SMEM>>>(0, 0, 1, 4, 0, 0, bo1, 1, N, Wo2, bo2, out, 1);
}

// round 16
// speedup vs baseline: 1.1249x; 1.0396x over previous
#include <cuda_runtime.h>
#include <cuda_bf16.h>
#include <cstdint>

#define MAXN 100000
#define MAXE 1600000
#define SCAN_B 1024
#define MAXSEG (2 * MAXN)

// ---------------- scratch (device globals; no runtime allocation) ----------
__device__ float g_bufA[MAXN * 128];        // 51.2 MB
__device__ float g_bufB[MAXN * 128];        // 51.2 MB
__device__ float g_bufC[MAXN * 128];        // 51.2 MB
__device__ float g_sums[MAXSEG * 128];      // 102.4 MB  per-(node,rel) means
__device__ int   g_flag[1];                 // 1 => indices are int64
// CSR over (dst,rel) segments
__device__ int   g_icnt[MAXSEG];
__device__ int   g_off[MAXSEG];
__device__ int   g_fill[MAXSEG];
__device__ int   g_bsum[256];
__device__ int   g_boff[256];
__device__ int   g_srcs[MAXE];
// pre-split, pre-transposed weights Bt[n][k], row-major bf16: [widx][hi/lo][32KB]
__device__ __align__(16) unsigned char g_wprep[5][2][32768];

__device__ __forceinline__ float* dbuf(int s) {
    return (s == 0) ? g_bufA : (s == 1) ? g_bufB : g_bufC;
}
__device__ __forceinline__ float lrelu(float v) { return v > 0.f ? v : 0.01f * v; }

// ---------------- mma.sync / cp.async helpers (sm_80+) ----------------------
__device__ __forceinline__ void ldsm_x4(uint32_t* r, uint32_t addr) {
    asm volatile("ldmatrix.sync.aligned.m8n8.x4.shared.b16 {%0,%1,%2,%3}, [%4];"
                 : "=r"(r[0]), "=r"(r[1]), "=r"(r[2]), "=r"(r[3]) : "r"(addr));
}
__device__ __forceinline__ void mma_bf16(float* c, const uint32_t* a, uint32_t b0, uint32_t b1) {
    asm volatile("mma.sync.aligned.m16n8k16.row.col.f32.bf16.bf16.f32 "
                 "{%0,%1,%2,%3}, {%4,%5,%6,%7}, {%8,%9}, {%0,%1,%2,%3};"
                 : "+f"(c[0]), "+f"(c[1]), "+f"(c[2]), "+f"(c[3])
                 : "r"(a[0]), "r"(a[1]), "r"(a[2]), "r"(a[3]), "r"(b0), "r"(b1));
}
__device__ __forceinline__ uint32_t smem_to_u32(const void* p) {
    uint32_t a;
    asm("{ .reg .u64 t; cvta.to.shared.u64 t, %1; cvt.u32.u64 %0, t; }" : "=r"(a) : "l"(p));
    return a;
}
__device__ __forceinline__ void cp_async16(uint32_t smem_addr, const void* gptr) {
    size_t ga = __cvta_generic_to_global((void*)gptr);
    asm volatile("cp.async.cg.shared.global [%0], [%1], 16;"
                 :: "r"(smem_addr), "l"(ga) : "memory");
}
__device__ __forceinline__ void cp_async_wait_all() {
    asm volatile("cp.async.commit_group;\ncp.async.wait_group 0;" ::: "memory");
}
__device__ __forceinline__ void bf16_split(float x, unsigned short& h, unsigned short& lo) {
    __nv_bfloat16 hh = __float2bfloat16_rn(x);
    float rl = x - __bfloat162float(hh);
    __nv_bfloat16 ll = __float2bfloat16_rn(rl);
    h = __bfloat16_as_ushort(hh);
    lo = __bfloat16_as_ushort(ll);
}

// SMEM tile geometry: rows of 136 bf16 (stride 272 B -> ldmatrix conflict-free)
// A tile: 64 rows; B tile: 128 n-rows. 2 CTAs/SM.
#define SROW 272
#define ABUF (64 * SROW)           // 17408 B per A image
#define BBUF (128 * SROW)          // 34816 B per B image
#define OFF_AHI 0
#define OFF_ALO (ABUF)
#define OFF_BHI (2 * ABUF)
#define OFF_BLO (2 * ABUF + BBUF)
#define TC_SMEM (2 * ABUF + 2 * BBUF)   // 104448 B

// ---------------- dtype detection + CSR zeroing -----------------------------
__global__ void detect_kernel(const int* __restrict__ ei, int n2) {
    __shared__ int s_nz;
    if (blockIdx.x == 0) {
        if (threadIdx.x == 0) s_nz = 0;
        __syncthreads();
        for (int p = threadIdx.x; p < 1024; p += blockDim.x)
            if (ei[2 * p + 1] != 0) s_nz = 1;
        __syncthreads();
        if (threadIdx.x == 0) g_flag[0] = (s_nz == 0) ? 1 : 0;
    }
    int i = blockIdx.x * 256 + threadIdx.x;
    if (i < n2) { g_icnt[i] = 0; g_fill[i] = 0; }
}

// ---------------- CSR build --------------------------------------------------
__global__ void icount_kernel(const void* __restrict__ ei, const void* __restrict__ et, int E) {
    int e = blockIdx.x * 256 + threadIdx.x;
    if (e >= E) return;
    long dst, typ;
    if (g_flag[0]) {
        dst = ((const long long*)ei)[(long)E + e];
        typ = ((const long long*)et)[e];
    } else {
        dst = ((const int*)ei)[E + e];
        typ = ((const int*)et)[e];
    }
    atomicAdd(&g_icnt[dst * 2 + typ], 1);
}

__global__ void scan_block_sums(int n2) {
    __shared__ int ssum[256];
    int base = blockIdx.x * SCAN_B;
    int tsum = 0;
    for (int i = threadIdx.x; i < SCAN_B; i += 256) {
        int idx = base + i;
        tsum += (idx < n2) ? g_icnt[idx] : 0;
    }
    ssum[threadIdx.x] = tsum;
    __syncthreads();
    for (int s = 128; s > 0; s >>= 1) {
        if (threadIdx.x < s) ssum[threadIdx.x] += ssum[threadIdx.x + s];
        __syncthreads();
    }
    if (threadIdx.x == 0) g_bsum[blockIdx.x] = ssum[0];
}

__global__ void scan_tops(int nb) {
    __shared__ int sv[256];
    int t = threadIdx.x;
    sv[t] = (t < nb) ? g_bsum[t] : 0;
    __syncthreads();
    if (t == 0) {
        int run = 0;
        for (int i = 0; i < nb; i++) { int c = sv[i]; sv[i] = run; run += c; }
    }
    __syncthreads();
    if (t < nb) g_boff[t] = sv[t];
}

__global__ void scan_offsets(int n2) {
    __shared__ int warpsum[8];
    int t = threadIdx.x;
    int base = blockIdx.x * SCAN_B + t * 4;
    int v[4];
    #pragma unroll
    for (int j = 0; j < 4; j++) v[j] = (base + j < n2) ? g_icnt[base + j] : 0;
    int tsum = v[0] + v[1] + v[2] + v[3];
    int lane = t & 31, wid = t >> 5;
    int x = tsum;
    #pragma unroll
    for (int o = 1; o < 32; o <<= 1) {
        int y = __shfl_up_sync(0xFFFFFFFFu, x, o);
        if (lane >= o) x += y;
    }
    if (lane == 31) warpsum[wid] = x;
    __syncthreads();
    if (t == 0) {
        int run = 0;
        for (int i = 0; i < 8; i++) { int c = warpsum[i]; warpsum[i] = run; run += c; }
    }
    __syncthreads();
    int ex = x - tsum + warpsum[wid] + g_boff[blockIdx.x];
    #pragma unroll
    for (int j = 0; j < 4; j++) {
        if (base + j < n2) g_off[base + j] = ex;
        ex += v[j];
    }
}

__global__ void fill_kernel(const void* __restrict__ ei, const void* __restrict__ et, int E) {
    int e = blockIdx.x * 256 + threadIdx.x;
    if (e >= E) return;
    long src, dst, typ;
    if (g_flag[0]) {
        const long long* p = (const long long*)ei;
        src = p[e]; dst = p[(long)E + e];
        typ = ((const long long*)et)[e];
    } else {
        const int* p = (const int*)ei;
        src = p[e]; dst = p[E + e];
        typ = ((const int*)et)[e];
    }
    int s = (int)(dst * 2 + typ);
    int pos = atomicAdd(&g_fill[s], 1);
    g_srcs[g_off[s] + pos] = (int)src;
}

// ---------------- mean aggregation: warp per (dst,rel) segment --------------
__global__ void mean_kernel(int selX, int n2) {
    int seg = blockIdx.x * 8 + (threadIdx.x >> 5);
    int lane = threadIdx.x & 31;
    if (seg >= n2) return;
    int deg = g_icnt[seg];
    int base = g_off[seg];
    const float4* X4 = (const float4*)dbuf(selX);
    float4 acc = make_float4(0.f, 0.f, 0.f, 0.f);
    int i = 0;
    for (; i + 4 <= deg; i += 4) {
        int s0 = g_srcs[base + i], s1 = g_srcs[base + i + 1];
        int s2 = g_srcs[base + i + 2], s3 = g_srcs[base + i + 3];
        float4 v0 = X4[(long)s0 * 32 + lane];
        float4 v1 = X4[(long)s1 * 32 + lane];
        float4 v2 = X4[(long)s2 * 32 + lane];
        float4 v3 = X4[(long)s3 * 32 + lane];
        acc.x += v0.x + v1.x + v2.x + v3.x;
        acc.y += v0.y + v1.y + v2.y + v3.y;
        acc.z += v0.z + v1.z + v2.z + v3.z;
        acc.w += v0.w + v1.w + v2.w + v3.w;
    }
    for (; i < deg; i++) {
        int s0 = g_srcs[base + i];
        float4 v0 = X4[(long)s0 * 32 + lane];
        acc.x += v0.x; acc.y += v0.y; acc.z += v0.z; acc.w += v0.w;
    }
    float sc = 1.0f / (float)max(deg, 1);
    acc.x *= sc; acc.y *= sc; acc.z *= sc; acc.w *= sc;
    ((float4*)g_sums)[(long)seg * 32 + lane] = acc;
}

// ---------------- weight prep: W[128,128] -> Bt[n][k] bf16 hi/lo ------------
__global__ void wprep_kernel(const float* __restrict__ Win, const float* __restrict__ Wrel,
                             const float* __restrict__ Wroot, const float* __restrict__ Wo1) {
    int w = blockIdx.x;
    const float* W = (w == 0) ? Win : (w == 1) ? Wrel : (w == 2) ? (Wrel + 16384)
                   : (w == 3) ? Wroot : Wo1;
    unsigned char* hi = g_wprep[w][0];
    unsigned char* lo = g_wprep[w][1];
    for (int i = threadIdx.x; i < 4096; i += blockDim.x) {
        int nrow = i >> 5;
        int k0 = (i & 31) * 4;
        unsigned short hs[4], ls[4];
        #pragma unroll
        for (int j = 0; j < 4; j++) {
            bf16_split(W[(k0 + j) * 128 + nrow], hs[j], ls[j]);   // Bt[n][k] = W[k][n]
        }
        uint32_t off = (uint32_t)nrow * 256u + (uint32_t)k0 * 2u;
        uint2 uh, ul;
        uh.x = (uint32_t)hs[0] | ((uint32_t)hs[1] << 16);
        uh.y = (uint32_t)hs[2] | ((uint32_t)hs[3] << 16);
        ul.x = (uint32_t)ls[0] | ((uint32_t)ls[1] << 16);
        ul.y = (uint32_t)ls[2] | ((uint32_t)ls[3] << 16);
        *(uint2*)(hi + off) = uh;
        *(uint2*)(lo + off) = ul;
    }
}

// ---------------- feature fusion: K=100 register-blocked kernel -------------
__global__ void fuse100_kernel(const float* __restrict__ des, const float* __restrict__ tw,
                               const float* __restrict__ Wd, const float* __restrict__ bd,
                               const float* __restrict__ Wt, const float* __restrict__ bt,
                               int n) {
    extern __shared__ float fsm[];
    float* sW = fsm;                 // 100*32 = 3200
    float* sIn = fsm + 3200;         // 128*100 = 12800
    float* sB = fsm + 3200 + 12800;  // 32
    int tid = threadIdx.x;
    int n0 = blockIdx.x * 128;
    int seg = blockIdx.y;
    const float* in = seg ? tw : des;
    const float* W = seg ? Wt : Wd;
    const float* B = seg ? bt : bd;

    for (int i = tid; i < 3200; i += 256) sW[i] = W[i];
    if (tid < 32) sB[tid] = B[tid];
    const float4* in4 = (const float4*)in;
    float4* sIn4 = (float4*)sIn;
    for (int i = tid; i < 128 * 25; i += 256) {
        int r = i / 25, c = i - r * 25;
        int row = n0 + r;
        sIn4[i] = (row < n) ? in4[(long)row * 25 + c] : make_float4(0.f, 0.f, 0.f, 0.f);
    }
    __syncthreads();

    int ng = tid >> 3;
    int cg = tid & 7;
    int c0 = cg * 4;
    float acc[4][4];
    #pragma unroll
    for (int j = 0; j < 4; j++) {
        acc[j][0] = sB[c0]; acc[j][1] = sB[c0 + 1];
        acc[j][2] = sB[c0 + 2]; acc[j][3] = sB[c0 + 3];
    }
    const float4* sW4 = (const float4*)sW;
    const float* a0 = sIn + (ng * 4 + 0) * 100;
    const float* a1 = sIn + (ng * 4 + 1) * 100;
    const float* a2 = sIn + (ng * 4 + 2) * 100;
    const float* a3 = sIn + (ng * 4 + 3) * 100;
    #pragma unroll 4
    for (int k = 0; k < 100; k++) {
        float4 wv = sW4[k * 8 + cg];
        float x0 = a0[k], x1 = a1[k], x2 = a2[k], x3 = a3[k];
        acc[0][0] += x0 * wv.x; acc[0][1] += x0 * wv.y; acc[0][2] += x0 * wv.z; acc[0][3] += x0 * wv.w;
        acc[1][0] += x1 * wv.x; acc[1][1] += x1 * wv.y; acc[1][2] += x1 * wv.z; acc[1][3] += x1 * wv.w;
        acc[2][0] += x2 * wv.x; acc[2][1] += x2 * wv.y; acc[2][2] += x2 * wv.z; acc[2][3] += x2 * wv.w;
        acc[3][0] += x3 * wv.x; acc[3][1] += x3 * wv.y; acc[3][2] += x3 * wv.z; acc[3][3] += x3 * wv.w;
    }
    #pragma unroll
    for (int j = 0; j < 4; j++) {
        int row = n0 + ng * 4 + j;
        if (row < n) {
            float4 o;
            o.x = lrelu(acc[j][0]); o.y = lrelu(acc[j][1]);
            o.z = lrelu(acc[j][2]); o.w = lrelu(acc[j][3]);
            *(float4*)(g_bufA + (long)row * 128 + seg * 32 + c0) = o;
        }
    }
}

// ---------------- feature fusion: small K (6, 11) ---------------------------
template<int K>
__device__ __forceinline__ void fuse_seg(const float* __restrict__ in,
                                         const float* __restrict__ W,
                                         const float* __restrict__ B,
                                         float* sW, float* sB, float* sIn,
                                         int n0, int n, int tid, int seg) {
    for (int i = tid; i < K * 32; i += 256) sW[i] = W[i];
    if (tid < 32) sB[tid] = B[tid];
    for (int i = tid; i < 64 * K; i += 256) {
        int r = i / K, c = i - r * K;
        int row = n0 + r;
        sIn[i] = (row < n) ? in[(long)row * K + c] : 0.f;
    }
    __syncthreads();

    int node = tid >> 2;
    int c0 = (tid & 3) * 8;
    float acc[8];
    #pragma unroll
    for (int j = 0; j < 8; j++) acc[j] = sB[c0 + j];
    const float4* sW4 = (const float4*)sW;
    int wbase = c0 >> 2;
    const float* aIn = sIn + node * K;
    #pragma unroll
    for (int k = 0; k < K; k++) {
        float a = aIn[k];
        float4 w0 = sW4[k * 8 + wbase];
        float4 w1 = sW4[k * 8 + wbase + 1];
        acc[0] += a * w0.x; acc[1] += a * w0.y; acc[2] += a * w0.z; acc[3] += a * w0.w;
        acc[4] += a * w1.x; acc[5] += a * w1.y; acc[6] += a * w1.z; acc[7] += a * w1.w;
    }
    int row = n0 + node;
    if (row < n) {
        float* o = g_bufA + (long)row * 128 + seg * 32 + c0;
        #pragma unroll
        for (int j = 0; j < 8; j++) o[j] = lrelu(acc[j]);
    }
}

__global__ void fuse_small_kernel(const float* __restrict__ nprop, const float* __restrict__ cprop,
                                  const float* __restrict__ Wn, const float* __restrict__ bn,
                                  const float* __restrict__ Wc, const float* __restrict__ bc,
                                  int n) {
    __shared__ __align__(16) float sW[11 * 32];
    __shared__ float sB[32];
    __shared__ __align__(16) float sIn[64 * 11];
    int tid = threadIdx.x;
    int n0 = blockIdx.x * 64;
    if (blockIdx.y == 0) fuse_seg<6> (nprop, Wn, bn, sW, sB, sIn, n0, n, tid, 2);
    else                 fuse_seg<11>(cprop, Wc, bc, sW, sB, sIn, n0, n, tid, 3);
}

// ---------------- mma.sync GEMM: 64-row tiles, 256 thr, 2 CTAs/SM -----------
// 8 warps. Warp w: rows (w>>1)*16..+15, cols (w&1)*64..+63.
// mode 0: 1 pass, A = dbuf(selX), weight w0.
// mode 1: 3 passes: p<2 A = g_sums rows (means); p=2 A = dbuf(selX).
// head==1 (requires mode==1): after the 3 combine passes, x2=acc+bias stays
// on-chip: bf16-split into A smem, B restaged with w3 (Wo1), second mma loop,
// then fused @Wo2+bo2 epilogue -> out2[N,2]. No x2 gmem roundtrip.
__global__ __launch_bounds__(256, 2)
void tc_gemm(int mode, int selX, int selC, int w0, int w1, int w2, int w3,
             const float* __restrict__ bias, const float* __restrict__ bias2,
             int act, int n,
             const float* __restrict__ Wo2, const float* __restrict__ bo2,
             float* __restrict__ out2, int head) {
    extern __shared__ unsigned char smm[];
    uint32_t sbase = smem_to_u32(smm);
    int tid = threadIdx.x;
    int w = tid >> 5;
    int l = tid & 31;
    int rw = (w >> 1) * 16;        // row base within 64-row tile
    int cb = (w & 1) * 64;         // col base
    int n0 = blockIdx.x * 64;

    float acc[8][4];
    #pragma unroll
    for (int t = 0; t < 8; t++) { acc[t][0] = acc[t][1] = acc[t][2] = acc[t][3] = 0.f; }

    uint32_t aRow = (uint32_t)(rw + (l & 15));
    uint32_t aAddrHi = sbase + OFF_AHI + aRow * SROW + ((uint32_t)(l >> 4)) * 16u;
    uint32_t aAddrLo = aAddrHi + (OFF_ALO - OFF_AHI);
    uint32_t bN = (uint32_t)(cb + (l & 7) + ((l >> 4) << 3));
    uint32_t bAddrHi = sbase + OFF_BHI + bN * SROW + ((uint32_t)((l >> 3) & 1)) * 16u;
    uint32_t bAddrLo = bAddrHi + (OFF_BLO - OFF_BHI);

    int npass = (mode == 1) ? 3 : 1;
    for (int p = 0; p < npass; p++) {
        if (p) __syncthreads();
        // stage B via cp.async (verbatim copy of pre-split bf16 images)
        int widx = (p == 0) ? w0 : (p == 1) ? w1 : w2;
        const uint4* bh = (const uint4*)g_wprep[widx][0];
        const uint4* bl = (const uint4*)g_wprep[widx][1];
        #pragma unroll
        for (int j = 0; j < 8; j++) {
            int i = tid + j * 256;
            uint32_t r = (uint32_t)(i >> 4), c = (uint32_t)(i & 15);
            uint32_t off = r * SROW + c * 16u;
            cp_async16(sbase + OFF_BHI + off, bh + i);
            cp_async16(sbase + OFF_BLO + off, bl + i);
        }
        // stage A: prefetch all global data first (MLP), then convert + STS
        bool from_sums = (mode == 1 && p < 2);
        const float4* X4 = (const float4*)dbuf(selX);
        float4 va[8];
        #pragma unroll
        for (int j = 0; j < 8; j++) {
            int i = tid + j * 256;
            int r = i >> 5, cg = i & 31;
            int row = n0 + r;
            va[j] = make_float4(0.f, 0.f, 0.f, 0.f);
            if (row < n) {
                if (from_sums) {
                    va[j] = ((const float4*)g_sums)[((long)row * 2 + p) * 32 + cg];
                } else {
                    va[j] = X4[(long)row * 32 + cg];
                }
            }
        }
        #pragma unroll
        for (int j = 0; j < 8; j++) {
            int i = tid + j * 256;
            int r = i >> 5, cg = i & 31;
            float x[4] = {va[j].x, va[j].y, va[j].z, va[j].w};
            unsigned short hs[4], ls[4];
            #pragma unroll
            for (int q = 0; q < 4; q++) bf16_split(x[q], hs[q], ls[q]);
            uint32_t off = (uint32_t)r * SROW + (uint32_t)cg * 8u;
            uint2 uh, ul;
            uh.x = (uint32_t)hs[0] | ((uint32_t)hs[1] << 16);
            uh.y = (uint32_t)hs[2] | ((uint32_t)hs[3] << 16);
            ul.x = (uint32_t)ls[0] | ((uint32_t)ls[1] << 16);
            ul.y = (uint32_t)ls[2] | ((uint32_t)ls[3] << 16);
            *(uint2*)(smm + OFF_AHI + off) = uh;
            *(uint2*)(smm + OFF_ALO + off) = ul;
        }
        cp_async_wait_all();
        __syncthreads();

        // compute: 8 k-steps x 4 n-groups (16 n each, this warp's half) x 3 terms
        for (int k0 = 0; k0 < 8; k0++) {
            uint32_t ah[4], al[4];
            ldsm_x4(ah, aAddrHi + (uint32_t)k0 * 32u);
            ldsm_x4(al, aAddrLo + (uint32_t)k0 * 32u);
            #pragma unroll
            for (int ng = 0; ng < 4; ng++) {
                uint32_t bhf[4], blf[4];
                uint32_t boff = (uint32_t)ng * (16u * SROW) + (uint32_t)k0 * 32u;
                ldsm_x4(bhf, bAddrHi + boff);   // non-trans: [n][k] is already col-major
                ldsm_x4(blf, bAddrLo + boff);
                mma_bf16(acc[2 * ng],     ah, bhf[0], bhf[1]);
                mma_bf16(acc[2 * ng],     ah, blf[0], blf[1]);
                mma_bf16(acc[2 * ng],     al, bhf[0], bhf[1]);
                mma_bf16(acc[2 * ng + 1], ah, bhf[2], bhf[3]);
                mma_bf16(acc[2 * ng + 1], ah, blf[2], blf[3]);
                mma_bf16(acc[2 * ng + 1], al, bhf[2], bhf[3]);
            }
        }
    }

    if (head) {
        // ---- merged head: x2 = acc + bias stays on-chip ----
        __syncthreads();    // all warps done reading A smem
        int r0loc = rw + (l >> 2);
        int r1loc = r0loc + 8;
        #pragma unroll
        for (int t = 0; t < 8; t++) {
            int col = cb + t * 8 + (l & 3) * 2;
            float b0 = bias[col], b1 = bias[col + 1];
            float v00 = acc[t][0] + b0, v01 = acc[t][1] + b1;   // row r0loc
            float v10 = acc[t][2] + b0, v11 = acc[t][3] + b1;   // row r1loc
            unsigned short h00, l00, h01, l01, h10, l10, h11, l11;
            bf16_split(v00, h00, l00); bf16_split(v01, h01, l01);
            bf16_split(v10, h10, l10); bf16_split(v11, h11, l11);
            uint32_t off0 = (uint32_t)r0loc * SROW + (uint32_t)col * 2u;
            uint32_t off1 = (uint32_t)r1loc * SROW + (uint32_t)col * 2u;
            *(uint32_t*)(smm + OFF_AHI + off0) = (uint32_t)h00 | ((uint32_t)h01 << 16);
            *(uint32_t*)(smm + OFF_ALO + off0) = (uint32_t)l00 | ((uint32_t)l01 << 16);
            *(uint32_t*)(smm + OFF_AHI + off1) = (uint32_t)h10 | ((uint32_t)h11 << 16);
            *(uint32_t*)(smm + OFF_ALO + off1) = (uint32_t)l10 | ((uint32_t)l11 << 16);
            acc[t][0] = acc[t][1] = acc[t][2] = acc[t][3] = 0.f;
        }
        // stage B = Wo1 (w3)
        {
            const uint4* bh = (const uint4*)g_wprep[w3][0];
            const uint4* bl = (const uint4*)g_wprep[w3][1];
            #pragma unroll
            for (int j = 0; j < 8; j++) {
                int i = tid + j * 256;
                uint32_t r = (uint32_t)(i >> 4), c = (uint32_t)(i & 15);
                uint32_t off = r * SROW + c * 16u;
                cp_async16(sbase + OFF_BHI + off, bh + i);
                cp_async16(sbase + OFF_BLO + off, bl + i);
            }
        }
        cp_async_wait_all();
        __syncthreads();
        for (int k0 = 0; k0 < 8; k0++) {
            uint32_t ah[4], al[4];
            ldsm_x4(ah, aAddrHi + (uint32_t)k0 * 32u);
            ldsm_x4(al, aAddrLo + (uint32_t)k0 * 32u);
            #pragma unroll
            for (int ng = 0; ng < 4; ng++) {
                uint32_t bhf[4], blf[4];
                uint32_t boff = (uint32_t)ng * (16u * SROW) + (uint32_t)k0 * 32u;
                ldsm_x4(bhf, bAddrHi + boff);
                ldsm_x4(blf, bAddrLo + boff);
                mma_bf16(acc[2 * ng],     ah, bhf[0], bhf[1]);
                mma_bf16(acc[2 * ng],     ah, blf[0], blf[1]);
                mma_bf16(acc[2 * ng],     al, bhf[0], bhf[1]);
                mma_bf16(acc[2 * ng + 1], ah, bhf[2], bhf[3]);
                mma_bf16(acc[2 * ng + 1], ah, blf[2], blf[3]);
                mma_bf16(acc[2 * ng + 1], al, bhf[2], bhf[3]);
            }
        }
        // fused head2: out2[row] = lrelu(acc+bias2) @ Wo2 + bo2
        float p00 = 0.f, p01 = 0.f, p10 = 0.f, p11 = 0.f;
        #pragma unroll
        for (int t = 0; t < 8; t++) {
            int col = cb + t * 8 + (l & 3) * 2;
            float b0 = bias2[col], b1 = bias2[col + 1];
            float w00 = Wo2[col * 2], w01 = Wo2[col * 2 + 1];
            float w10 = Wo2[(col + 1) * 2], w11 = Wo2[(col + 1) * 2 + 1];
            float o0 = lrelu(acc[t][0] + b0), o1 = lrelu(acc[t][1] + b1);
            p00 += o0 * w00 + o1 * w10;  p01 += o0 * w01 + o1 * w11;
            float o2 = lrelu(acc[t][2] + b0), o3 = lrelu(acc[t][3] + b1);
            p10 += o2 * w00 + o3 * w10;  p11 += o2 * w01 + o3 * w11;
        }
        #pragma unroll
        for (int m = 1; m <= 2; m <<= 1) {
            p00 += __shfl_xor_sync(0xFFFFFFFFu, p00, m);
            p01 += __shfl_xor_sync(0xFFFFFFFFu, p01, m);
            p10 += __shfl_xor_sync(0xFFFFFFFFu, p10, m);
            p11 += __shfl_xor_sync(0xFFFFFFFFu, p11, m);
        }
        __syncthreads();
        float* scratch = (float*)(smm + OFF_BHI);   // 64 rows x 2 floats
        if ((w & 1) == 0 && (l & 3) == 0) {
            scratch[r0loc * 2 + 0] = p00;  scratch[r0loc * 2 + 1] = p01;
            scratch[r1loc * 2 + 0] = p10;  scratch[r1loc * 2 + 1] = p11;
        }
        __syncthreads();
        if ((w & 1) == 1 && (l & 3) == 0) {
            int row0 = n0 + r0loc, row1 = n0 + r1loc;
            float c0 = bo2[0], c1 = bo2[1];
            if (row0 < n) {
                out2[row0 * 2 + 0] = scratch[r0loc * 2 + 0] + p00 + c0;
                out2[row0 * 2 + 1] = scratch[r0loc * 2 + 1] + p01 + c1;
            }
            if (row1 < n) {
                out2[row1 * 2 + 0] = scratch[r1loc * 2 + 0] + p10 + c0;
                out2[row1 * 2 + 1] = scratch[r1loc * 2 + 1] + p11 + c1;
            }
        }
        return;
    }

    float* C = dbuf(selC);
    int r0 = n0 + rw + (l >> 2);
    int r1 = r0 + 8;
    #pragma unroll
    for (int t = 0; t < 8; t++) {
        int col = cb + t * 8 + (l & 3) * 2;
        float b0 = bias[col], b1 = bias[col + 1];
        if (r0 < n) {
            float2 o;
            o.x = acc[t][0] + b0; o.y = acc[t][1] + b1;
            if (act) { o.x = lrelu(o.x); o.y = lrelu(o.y); }
            *(float2*)(C + (long)r0 * 128 + col) = o;
        }
        if (r1 < n) {
            float2 o;
            o.x = acc[t][2] + b0; o.y = acc[t][3] + b1;
            if (act) { o.x = lrelu(o.x); o.y = lrelu(o.y); }
            *(float2*)(C + (long)r1 * 128 + col) = o;
        }
    }
}

// ---------------- host ------------------------------------------------------
extern "C" void kernel_launch(void* const* d_in, const int* in_sizes, int n_in,
                              void* d_out, int out_size) {
    const float* des  = (const float*)d_in[0];
    const float* tw   = (const float*)d_in[1];
    const float* npr  = (const float*)d_in[2];
    const float* cpr  = (const float*)d_in[3];
    const void*  ei   = d_in[4];
    const void*  et   = d_in[5];
    const float* Wd   = (const float*)d_in[6];  const float* bd  = (const float*)d_in[7];
    const float* Wt   = (const float*)d_in[8];  const float* bt  = (const float*)d_in[9];
    const float* Wn   = (const float*)d_in[10]; const float* bn  = (const float*)d_in[11];
    const float* Wc   = (const float*)d_in[12]; const float* bc  = (const float*)d_in[13];
    const float* Win  = (const float*)d_in[14]; const float* bin = (const float*)d_in[15];
    const float* Wrel = (const float*)d_in[16];
    const float* Wroot= (const float*)d_in[17];
    const float* brg  = (const float*)d_in[18];
    const float* Wo1  = (const float*)d_in[19]; const float* bo1 = (const float*)d_in[20];
    const float* Wo2  = (const float*)d_in[21]; const float* bo2 = (const float*)d_in[22];
    float* out = (float*)d_out;

    int N = in_sizes[0] / 100;
    int E = in_sizes[5];
    int n2 = 2 * N;
    int nb_scan = (n2 + SCAN_B - 1) / SCAN_B;

    const int FUSE_SMEM = (3200 + 12800 + 32) * 4;   // 64128 B
    cudaFuncSetAttribute(tc_gemm, cudaFuncAttributeMaxDynamicSharedMemorySize, TC_SMEM);
    cudaFuncSetAttribute(fuse100_kernel, cudaFuncAttributeMaxDynamicSharedMemorySize, FUSE_SMEM);

    int nb64 = (N + 63) / 64;
    int nb128 = (N + 127) / 128;
    int eb = (E + 255) / 256;

    // launch order puts tc_gemm at position 6 (ncu capture window: -s 5 -c 1)
    detect_kernel<<<(n2 + 255) / 256, 256>>>((const int*)ei, n2);           // 1
    wprep_kernel<<<5, 256>>>(Win, Wrel, Wroot, Wo1);                        // 2
    fuse100_kernel<<<dim3(nb128, 2), 256, FUSE_SMEM>>>(des, tw, Wd, bd, Wt, bt, N);  // 3
    fuse_small_kernel<<<dim3(nb64, 2), 256>>>(npr, cpr, Wn, bn, Wc, bc, N); // 4
    icount_kernel<<<eb, 256>>>(ei, et, E);                                  // 5
    tc_gemm<<<nb64, 256, TC_SMEM>>>(0, 0, 1, 0, 0, 0, 0, bin, 0, 1, N, 0, 0, 0, 0); // 6: bufA->bufB

    scan_block_sums<<<nb_scan, 256>>>(n2);
    scan_tops<<<1, 256>>>(nb_scan);
    scan_offsets<<<nb_scan, 256>>>(n2);
    fill_kernel<<<eb, 256>>>(ei, et, E);

    mean_kernel<<<(n2 + 7) / 8, 256>>>(1, n2);                              // x0 means
    tc_gemm<<<nb64, 256, TC_SMEM>>>(1, 1, 2, 1, 2, 3, 0, brg, 0, 0, N, 0, 0, 0, 0); // -> bufC

    mean_kernel<<<(n2 + 7) / 8, 256>>>(2, n2);                              // x1 means
    // combine2 + head1 + head2 fused (x2 never leaves the CTA)
    tc_gemm<<<nb64, 256, TC_SMEM>>>(1, 2, 0, 1, 2, 3, 4, brg, bo1, 0, N, Wo2, bo2, out, 1);
}